// round 11
// baseline (speedup 1.0000x reference)
#include <cuda_runtime.h>
#include <cuda_bf16.h>
#include <cstdint>

#define T_STEPS 1024
#define H_DIM   768
#define B_DIM   32
#define G_DIM   (3*H_DIM)     // 2304
#define K2      1536          // [hi|lo] packed K for GEMM
#define KBIG    2304          // 3-term K for recurrent W_hh
#define M_BIG   (T_STEPS*B_DIM) // 32768
#define RCTAS 96

// ---------------- static device scratch ----------------
__device__ float g_xg[(size_t)T_STEPS * G_DIM * B_DIM];
__device__ float g_actA[(size_t)T_STEPS * H_DIM * B_DIM];
__device__ float g_actB[(size_t)T_STEPS * H_DIM * B_DIM];
__device__ __align__(1024) __nv_bfloat16 g_Abig[(size_t)M_BIG * K2];
__device__ __align__(1024) __nv_bfloat16 g_Wbig[(size_t)4 * G_DIM * K2];
__device__ __align__(1024) __nv_bfloat16 g_WhhBig[(size_t)4 * G_DIM * KBIG];
__device__ __align__(256) __nv_bfloat16 g_hs[2][1536 * B_DIM];
// contention-free barrier: one 128B line per CTA + broadcast word
__device__ volatile unsigned g_flags[RCTAS * 32];
__device__ volatile unsigned g_gen;

// ---------------- bf16 two-term split helpers ----------------
__device__ __forceinline__ void split_bf16(float v, __nv_bfloat16& hi, __nv_bfloat16& lo) {
    hi = __float2bfloat16(v);
    lo = __float2bfloat16(v - __bfloat162float(hi));
}
__device__ __forceinline__ float fast_sigmoid(float x) {
    return __fdividef(1.f, 1.f + __expf(-x));
}
__device__ __forceinline__ float fast_tanh(float x) {
    return 2.f * __fdividef(1.f, 1.f + __expf(-2.f * x)) - 1.f;
}

// ---------------- split kernels ----------------
__global__ void __launch_bounds__(256) split_x0(const float* __restrict__ x,
                                                __nv_bfloat16* __restrict__ Ab) {
    int t = blockIdx.x;
    for (int i = threadIdx.x; i < 32 * H_DIM; i += 256) {
        int b = i / H_DIM, d = i % H_DIM;
        float v = x[((size_t)b * T_STEPS + t) * H_DIM + d];
        __nv_bfloat16 hi, lo; split_bf16(v, hi, lo);
        size_t r = ((size_t)t * 32 + b) * K2;
        Ab[r + d] = hi;
        Ab[r + 768 + d] = lo;
    }
}

__global__ void __launch_bounds__(256) split_act(const float* __restrict__ act,
                                                 __nv_bfloat16* __restrict__ Ab) {
    __shared__ float sm[64][33];
    int t = blockIdx.x;
    int d0 = blockIdx.y * 64;
    int ts = T_STEPS - 1 - t;
    for (int i = threadIdx.x; i < 64 * 32; i += 256) {
        int dl = i >> 5, b = i & 31;
        sm[dl][b] = act[((size_t)ts * H_DIM + d0 + dl) * B_DIM + b];
    }
    __syncthreads();
    for (int i = threadIdx.x; i < 32 * 64; i += 256) {
        int b = i >> 6, dl = i & 63;
        float v = sm[dl][b];
        __nv_bfloat16 hi, lo; split_bf16(v, hi, lo);
        size_t r = ((size_t)t * 32 + b) * K2;
        Ab[r + d0 + dl] = hi;
        Ab[r + 768 + d0 + dl] = lo;
    }
}

__global__ void __launch_bounds__(256) split_w2(const float* __restrict__ W,
                                                __nv_bfloat16* __restrict__ Wb) {
    int i = blockIdx.x * 256 + threadIdx.x;
    if (i >= G_DIM * H_DIM) return;
    int g = i / H_DIM, d = i % H_DIM;
    float v = W[i];
    __nv_bfloat16 hi, lo; split_bf16(v, hi, lo);
    size_t r = (size_t)g * K2;
    Wb[r + d] = hi;
    Wb[r + 768 + d] = lo;
}

__global__ void __launch_bounds__(256) split_w(const float* __restrict__ W,
                                               __nv_bfloat16* __restrict__ Wb) {
    int i = blockIdx.x * 256 + threadIdx.x;
    if (i >= G_DIM * H_DIM) return;
    int g = i / H_DIM, d = i % H_DIM;
    float v = W[i];
    __nv_bfloat16 hi, lo; split_bf16(v, hi, lo);
    size_t r = (size_t)g * KBIG;
    Wb[r + d] = hi;
    Wb[r + 768 + d] = hi;
    Wb[r + 1536 + d] = lo;
}

// fused layer-0 splits + barrier reset (runs first every graph replay)
__global__ void __launch_bounds__(256) split_l0(const float* __restrict__ Wih0,
                                                const float* __restrict__ Whh0,
                                                __nv_bfloat16* __restrict__ Wb,
                                                __nv_bfloat16* __restrict__ Whh) {
    if (blockIdx.x == 0) {
        if (threadIdx.x < RCTAS) g_flags[threadIdx.x << 5] = 0u;
        if (threadIdx.x == RCTAS) g_gen = 0u;
    }
    int half = gridDim.x >> 1;
    if (blockIdx.x < half) {
        int i = blockIdx.x * 256 + threadIdx.x;
        if (i >= G_DIM * H_DIM) return;
        int g = i / H_DIM, d = i % H_DIM;
        float v = Wih0[i];
        __nv_bfloat16 hi, lo; split_bf16(v, hi, lo);
        size_t r = (size_t)g * K2;
        Wb[r + d] = hi;
        Wb[r + 768 + d] = lo;
    } else {
        int i = (blockIdx.x - half) * 256 + threadIdx.x;
        if (i >= G_DIM * H_DIM) return;
        int g = i / H_DIM, d = i % H_DIM;
        float v = Whh0[i];
        __nv_bfloat16 hi, lo; split_bf16(v, hi, lo);
        size_t r = (size_t)g * KBIG;
        Whh[r + d] = hi;
        Whh[r + 768 + d] = hi;
        Whh[r + 1536 + d] = lo;
    }
}

// ---------------- common asm helpers ----------------
__device__ __forceinline__ void cp16(void* s, const void* g) {
    uint32_t sa = (uint32_t)__cvta_generic_to_shared(s);
    asm volatile("cp.async.cg.shared.global [%0], [%1], 16;\n" :: "r"(sa), "l"(g));
}
__device__ __forceinline__ void cp16a(uint32_t sa, const void* g) {
    asm volatile("cp.async.cg.shared.global [%0], [%1], 16;\n" :: "r"(sa), "l"(g));
}
__device__ __forceinline__ void ldsm_x4(uint32_t& r0, uint32_t& r1, uint32_t& r2, uint32_t& r3,
                                        const __nv_bfloat16* p) {
    uint32_t a = (uint32_t)__cvta_generic_to_shared(p);
    asm volatile("ldmatrix.sync.aligned.m8n8.x4.shared.b16 {%0,%1,%2,%3}, [%4];\n"
                 : "=r"(r0), "=r"(r1), "=r"(r2), "=r"(r3) : "r"(a));
}
__device__ __forceinline__ void ldsm_x4a(uint32_t& r0, uint32_t& r1, uint32_t& r2, uint32_t& r3,
                                         uint32_t a) {
    asm volatile("ldmatrix.sync.aligned.m8n8.x4.shared.b16 {%0,%1,%2,%3}, [%4];\n"
                 : "=r"(r0), "=r"(r1), "=r"(r2), "=r"(r3) : "r"(a));
}
__device__ __forceinline__ void ldsm_x4t(uint32_t& r0, uint32_t& r1, uint32_t& r2, uint32_t& r3,
                                         uint32_t a) {
    asm volatile("ldmatrix.sync.aligned.m8n8.x4.trans.shared.b16 {%0,%1,%2,%3}, [%4];\n"
                 : "=r"(r0), "=r"(r1), "=r"(r2), "=r"(r3) : "r"(a));
}
__device__ __forceinline__ void mma_bf16(float* c, const uint32_t* a, const uint32_t* b) {
    asm volatile("mma.sync.aligned.m16n8k16.row.col.f32.bf16.bf16.f32 "
                 "{%0,%1,%2,%3}, {%4,%5,%6,%7}, {%8,%9}, {%0,%1,%2,%3};\n"
                 : "+f"(c[0]), "+f"(c[1]), "+f"(c[2]), "+f"(c[3])
                 : "r"(a[0]), "r"(a[1]), "r"(a[2]), "r"(a[3]), "r"(b[0]), "r"(b[1]));
}

// ---------------- input-projection GEMM (unchanged) ----------------
#define SPITCH 40
#define T1 (128 * SPITCH)
#define STG2 (4 * T1)
#define GITER 24

__global__ void __launch_bounds__(256, 1) gemm_tc(
    const __nv_bfloat16* __restrict__ A,
    const __nv_bfloat16* __restrict__ Wb,
    const float* __restrict__ bias,
    float* __restrict__ xg)
{
    extern __shared__ char smem_raw[];
    __nv_bfloat16* sm = (__nv_bfloat16*)smem_raw;

    const int tid = threadIdx.x;
    const int lane = tid & 31;
    const int warp = tid >> 5;
    const int wm = warp >> 1;
    const int wn = warp & 1;
    const int gBase = blockIdx.x * 128;
    const int mBase = blockIdx.y * 128;

    float acc[2][8][4];
#pragma unroll
    for (int i = 0; i < 2; ++i)
#pragma unroll
        for (int j = 0; j < 8; ++j)
#pragma unroll
            for (int k = 0; k < 4; ++k) acc[i][j][k] = 0.f;

    auto load_tile = [&](int stage, int it) {
        __nv_bfloat16* base = sm + stage * STG2;
        int k0 = it * 32;
        int c = tid & 3;
        int rhalf = tid >> 2;
#pragma unroll
        for (int j = 0; j < 8; ++j) {
            int tile = j >> 1;
            int row = (j & 1) * 64 + rhalf;
            const __nv_bfloat16* src =
                (tile < 2 ? A + (size_t)(mBase + row) * K2
                          : Wb + (size_t)(gBase + row) * K2)
                + (tile & 1) * 768 + k0 + c * 8;
            cp16(base + tile * T1 + row * SPITCH + c * 8, src);
        }
    };

#pragma unroll
    for (int s = 0; s < 3; ++s) {
        load_tile(s, s);
        asm volatile("cp.async.commit_group;\n" ::: "memory");
    }

    for (int it = 0; it < GITER; ++it) {
        asm volatile("cp.async.wait_group %0;\n" :: "n"(2) : "memory");
        __syncthreads();
        int itn = it + 3;
        if (itn < GITER) load_tile(itn & 3, itn);
        asm volatile("cp.async.commit_group;\n" ::: "memory");

        const __nv_bfloat16* Ah = sm + (it & 3) * STG2;
        const __nv_bfloat16* Al = Ah + T1;
        const __nv_bfloat16* Wh = Ah + 2 * T1;
        const __nv_bfloat16* Wl = Ah + 3 * T1;
#pragma unroll
        for (int kk = 0; kk < 2; ++kk) {
            uint32_t afh[2][4], afl[2][4];
            uint32_t bfh[8][2], bfl[8][2];
#pragma unroll
            for (int mt = 0; mt < 2; ++mt) {
                int ro = (wm * 32 + mt * 16 + (lane & 15)) * SPITCH + kk * 16 + (lane >> 4) * 8;
                ldsm_x4(afh[mt][0], afh[mt][1], afh[mt][2], afh[mt][3], Ah + ro);
                ldsm_x4(afl[mt][0], afl[mt][1], afl[mt][2], afl[mt][3], Al + ro);
            }
#pragma unroll
            for (int np = 0; np < 4; ++np) {
                int grp = lane >> 3;
                int ro = (wn * 64 + np * 16 + (grp >> 1) * 8 + (lane & 7)) * SPITCH
                       + kk * 16 + (grp & 1) * 8;
                uint32_t r0, r1, r2, r3;
                ldsm_x4(r0, r1, r2, r3, Wh + ro);
                bfh[2 * np][0] = r0; bfh[2 * np][1] = r1;
                bfh[2 * np + 1][0] = r2; bfh[2 * np + 1][1] = r3;
                ldsm_x4(r0, r1, r2, r3, Wl + ro);
                bfl[2 * np][0] = r0; bfl[2 * np][1] = r1;
                bfl[2 * np + 1][0] = r2; bfl[2 * np + 1][1] = r3;
            }
#pragma unroll
            for (int mt = 0; mt < 2; ++mt)
#pragma unroll
                for (int nt = 0; nt < 8; ++nt) {
                    mma_bf16(acc[mt][nt], afh[mt], bfh[nt]);
                    mma_bf16(acc[mt][nt], afl[mt], bfh[nt]);
                    mma_bf16(acc[mt][nt], afh[mt], bfl[nt]);
                }
        }
    }
    asm volatile("cp.async.wait_all;\n" ::: "memory");
    __syncthreads();

    float* ebuf = (float*)smem_raw + warp * (64 * 33);
#pragma unroll
    for (int mt = 0; mt < 2; ++mt)
#pragma unroll
        for (int nt = 0; nt < 8; ++nt) {
            int b0 = mt * 16 + (lane >> 2);
            int gl = nt * 8 + (lane & 3) * 2;
            ebuf[gl * 33 + b0]            = acc[mt][nt][0];
            ebuf[(gl + 1) * 33 + b0]      = acc[mt][nt][1];
            ebuf[gl * 33 + b0 + 8]        = acc[mt][nt][2];
            ebuf[(gl + 1) * 33 + b0 + 8]  = acc[mt][nt][3];
        }
    __syncwarp();
    int t = blockIdx.y * 4 + wm;
    int g0 = gBase + wn * 64;
    size_t obase = (size_t)t * (G_DIM * B_DIM);
#pragma unroll 4
    for (int g = 0; g < 64; ++g) {
        xg[obase + (size_t)(g0 + g) * B_DIM + lane] = ebuf[g * 33 + lane] + bias[g0 + g];
    }
}
#define GEMM_SMEM ((4 * STG2 * 2 > 8 * 64 * 33 * 4) ? 4 * STG2 * 2 : 8 * 64 * 33 * 4)

// ================= tensor-core recurrent kernel =================
#define RTHR  384
#define WPITCH 2312
#define SM_W_BYTES (24 * WPITCH * 2)
#define SM_H_OFF   SM_W_BYTES
#define SM_H_BYTES (1536 * 64)
#define SM_PART_OFF (SM_H_OFF + SM_H_BYTES)
#define SM_PART_BYTES (12 * 2 * 4 * 32 * 4)
#define SM_BSH_OFF (SM_PART_OFF + SM_PART_BYTES)
#define SM_REC_TOTAL (SM_BSH_OFF + 128)

__device__ __forceinline__ uint32_t hs_chunk(int k, int c) {
    return (uint32_t)((k >> 1) * 8 + ((((k & 1) << 2) | c) ^ ((k >> 1) & 7)));
}

__global__ void __launch_bounds__(RTHR, 1) gru_rec_tc(
    const __nv_bfloat16* __restrict__ WhhB,
    const float* __restrict__ bhh,
    const float* __restrict__ xg,
    const float* __restrict__ res,
    float* __restrict__ out,
    int out_mode,
    int epoch_base)
{
    extern __shared__ __align__(1024) char smr[];
    __nv_bfloat16* Wsm = (__nv_bfloat16*)smr;
    const uint32_t hs_base = (uint32_t)__cvta_generic_to_shared(smr + SM_H_OFF);
    float* part = (float*)(smr + SM_PART_OFF);
    float* bsh  = (float*)(smr + SM_BSH_OFF);

    const int tid = threadIdx.x;
    const int lane = tid & 31;
    const int w = tid >> 5;
    const int kq = w & 3;
    const int nt = w >> 2;
    const int cta = blockIdx.x;

#pragma unroll
    for (int i = 0; i < 18; ++i) {
        int task = i * RTHR + tid;
        int n = task / 288, c = task % 288;
        int grow = (n >> 3) * H_DIM + cta * 8 + (n & 7);
        cp16(Wsm + n * WPITCH + c * 8, WhhB + (size_t)grow * KBIG + c * 8);
    }
    if (tid < 24) {
        int gt = tid >> 3, jl = tid & 7;
        bsh[tid] = bhh[gt * H_DIM + cta * 8 + jl];
    }
    if (tid < 256) {
        int jl = tid >> 5, j = cta * 8 + jl;
        g_hs[0][j * B_DIM + lane] = __float2bfloat16(0.f);
        g_hs[0][(768 + j) * B_DIM + lane] = __float2bfloat16(0.f);
    }
    asm volatile("cp.async.commit_group;\n" ::: "memory");
    asm volatile("cp.async.wait_all;\n" ::: "memory");
    __threadfence();   // publish h zeros (all threads) — proven writer-side protocol

    const int jlf = tid >> 5;
    const int jgf = cta * 8 + jlf;

    // step-0 gate-input prefetch (stream-ordered data, safe before barrier)
    float xr = 0.f, xz = 0.f, xn = 0.f, rv = 0.f;
    auto prefetch = [&](int t) {
        if (tid < 256) {
            size_t base = (size_t)t * (G_DIM * B_DIM);
            xr = xg[base + (size_t)(0 * H_DIM + jgf) * B_DIM + lane];
            xz = xg[base + (size_t)(1 * H_DIM + jgf) * B_DIM + lane];
            xn = xg[base + (size_t)(2 * H_DIM + jgf) * B_DIM + lane];
            if (res)
                rv = res[(size_t)(T_STEPS - 1 - t) * (H_DIM * B_DIM) +
                         (size_t)jgf * B_DIM + lane];
        }
    };

    // ---- contention-free grid barrier ----
    // arrive: plain volatile store of monotone epoch to own L2 line.
    // CTA0 tid0 sweeps all flags (pipelined volatile loads), fences, broadcasts g_gen.
    // Others spin on g_gen. Single-thread read->fence->write chains keep the
    // proven cumulativity structure; writer-side fences are untouched.
    auto barrier_wait = [&](unsigned target) {
        if (cta == 0) {
            if (tid == 0) {
                unsigned ok;
                do {
                    ok = 1u;
#pragma unroll
                    for (int i = 0; i < RCTAS; i += 8) {
                        unsigned v0 = g_flags[(i + 0) << 5];
                        unsigned v1 = g_flags[(i + 1) << 5];
                        unsigned v2 = g_flags[(i + 2) << 5];
                        unsigned v3 = g_flags[(i + 3) << 5];
                        unsigned v4 = g_flags[(i + 4) << 5];
                        unsigned v5 = g_flags[(i + 5) << 5];
                        unsigned v6 = g_flags[(i + 6) << 5];
                        unsigned v7 = g_flags[(i + 7) << 5];
                        ok &= (unsigned)(v0 >= target) & (unsigned)(v1 >= target)
                            & (unsigned)(v2 >= target) & (unsigned)(v3 >= target)
                            & (unsigned)(v4 >= target) & (unsigned)(v5 >= target)
                            & (unsigned)(v6 >= target) & (unsigned)(v7 >= target);
                    }
                } while (!ok);
                __threadfence();
                g_gen = target;
            }
        } else {
            if (tid == 0) {
                while (g_gen < target) { }
                __threadfence();
            }
        }
        __syncthreads();
    };

    prefetch(0);

    // initial barrier
    __syncthreads();
    if (tid == 0) g_flags[cta << 5] = (unsigned)(epoch_base + 1);
    barrier_wait((unsigned)(epoch_base + 1));

    const int t4 = lane >> 3, r8 = lane & 7;
    const uint32_t w_base = (uint32_t)__cvta_generic_to_shared(Wsm)
                          + (uint32_t)((nt * 8 + r8) * WPITCH * 2 + t4 * 16);
    const int a_roff = ((t4 >> 1) << 3) + r8;
    const int a_c0 = (t4 & 1);

    auto a_addr = [&](int kt, int mt) -> uint32_t {
        int hrow = (kt < 96 ? kt : kt - 96) << 4;
        int krow = hrow + a_roff;
        int c = mt * 2 + a_c0;
        return hs_base + hs_chunk(krow, c) * 16;
    };

    const int mtF = lane >> 4, m_in = lane & 15;
    const int lane_src = (m_in & 7) * 4 + (jlf >> 1);
    const int regF = (jlf & 1) + 2 * (m_in >> 3);
    float hprev = 0.f;

    for (int t = 0; t < T_STEPS; ++t) {
        // stage h: group0 = hi rows, group1 = lo rows
        const __nv_bfloat16* hsrc = g_hs[t & 1];
#pragma unroll
        for (int i = 0; i < 8; ++i) {
            int task = i * RTHR + tid;
            int k = task >> 2, c = task & 3;
            cp16a(hs_base + hs_chunk(k, c) * 16, hsrc + k * B_DIM + c * 8);
        }
        asm volatile("cp.async.commit_group;\n" ::: "memory");
#pragma unroll
        for (int i = 8; i < 16; ++i) {
            int task = i * RTHR + tid;
            int k = task >> 2, c = task & 3;
            cp16a(hs_base + hs_chunk(k, c) * 16, hsrc + k * B_DIM + c * 8);
        }
        asm volatile("cp.async.commit_group;\n" ::: "memory");

        float acc0[4] = {0.f, 0.f, 0.f, 0.f};
        float acc1[4] = {0.f, 0.f, 0.f, 0.f};

        auto do_pairAB = [&](int q) {
            uint32_t a0 = a_addr(2 * q, 0);
            uint32_t a1 = a_addr(2 * q, 1);
            uint32_t fA0[4], fA1[4], fB0[4], fB1[4];
            ldsm_x4t(fA0[0], fA0[1], fA0[2], fA0[3], a0);
            ldsm_x4t(fA1[0], fA1[1], fA1[2], fA1[3], a1);
            ldsm_x4t(fB0[0], fB0[1], fB0[2], fB0[3], a0 + 1024);
            ldsm_x4t(fB1[0], fB1[1], fB1[2], fB1[3], a1 + 1024);
            uint32_t b0, b1, b2, b3;
            ldsm_x4a(b0, b1, b2, b3, w_base + (uint32_t)(q * 64));
            { uint32_t bA[2] = {b0, b1}, bB[2] = {b2, b3};
              mma_bf16(acc0, fA0, bA); mma_bf16(acc1, fA1, bA);
              mma_bf16(acc0, fB0, bB); mma_bf16(acc1, fB1, bB); }
            ldsm_x4a(b0, b1, b2, b3, w_base + (uint32_t)((q + 48) * 64));
            { uint32_t bA[2] = {b0, b1}, bB[2] = {b2, b3};
              mma_bf16(acc0, fA0, bA); mma_bf16(acc1, fA1, bA);
              mma_bf16(acc0, fB0, bB); mma_bf16(acc1, fB1, bB); }
        };
        auto do_pair = [&](int q) {
            uint32_t b0, b1, b2, b3;
            ldsm_x4a(b0, b1, b2, b3, w_base + (uint32_t)(q * 64));
            uint32_t bA[2] = {b0, b1}, bB[2] = {b2, b3};
            uint32_t a0 = a_addr(2 * q, 0);
            uint32_t a1 = a_addr(2 * q, 1);
            uint32_t af[4];
            ldsm_x4t(af[0], af[1], af[2], af[3], a0);
            mma_bf16(acc0, af, bA);
            ldsm_x4t(af[0], af[1], af[2], af[3], a1);
            mma_bf16(acc1, af, bA);
            ldsm_x4t(af[0], af[1], af[2], af[3], a0 + 1024);
            mma_bf16(acc0, af, bB);
            ldsm_x4t(af[0], af[1], af[2], af[3], a1 + 1024);
            mma_bf16(acc1, af, bB);
        };

        asm volatile("cp.async.wait_group %0;\n" :: "n"(1) : "memory");
        __syncthreads();
#pragma unroll
        for (int p = 0; p < 6; ++p) do_pairAB(kq + 4 * p);

        asm volatile("cp.async.wait_group %0;\n" :: "n"(0) : "memory");
        __syncthreads();
#pragma unroll
        for (int p = 0; p < 6; ++p) do_pair(24 + kq + 4 * p);

#pragma unroll
        for (int rg = 0; rg < 4; ++rg) {
            part[((w * 2 + 0) * 4 + rg) * 32 + lane] = acc0[rg];
            part[((w * 2 + 1) * 4 + rg) * 32 + lane] = acc1[rg];
        }
        __syncthreads();

        // finalize: gates, h store, out store, per-writer fence (proven R8 form)
        if (tid < 256) {
            float g3[3];
#pragma unroll
            for (int gt = 0; gt < 3; ++gt) {
                float s = 0.f;
#pragma unroll
                for (int k4 = 0; k4 < 4; ++k4) {
                    int wsrc = gt * 4 + k4;
                    s += part[((wsrc * 2 + mtF) * 4 + regF) * 32 + lane_src];
                }
                g3[gt] = s + bsh[gt * 8 + jlf];
            }
            float r = fast_sigmoid(xr + g3[0]);
            float z = fast_sigmoid(xz + g3[1]);
            float n = fast_tanh(xn + r * g3[2]);
            float hv = (1.f - z) * n + z * hprev;
            hprev = hv;
            __nv_bfloat16 hi, lo; split_bf16(hv, hi, lo);
            __nv_bfloat16* hdst = g_hs[(t & 1) ^ 1];
            hdst[jgf * B_DIM + lane] = hi;
            hdst[(768 + jgf) * B_DIM + lane] = lo;
            float ov = rv + hv;
            if (out_mode == 0)
                out[(size_t)t * (H_DIM * B_DIM) + (size_t)jgf * B_DIM + lane] = ov;
            else
                out[((size_t)lane * T_STEPS + (T_STEPS - 1 - t)) * H_DIM + jgf] = ov;
            __threadfence();
        }

        // barrier: sync -> flag arrive -> prefetch window -> wait -> sync
        __syncthreads();
        unsigned target = (unsigned)(epoch_base + 2 + t);
        if (tid == 0) g_flags[cta << 5] = target;
        if (t + 1 < T_STEPS) prefetch(t + 1);
        barrier_wait(target);
    }
}

// ---------------- host launcher ----------------
extern "C" void kernel_launch(void* const* d_in, const int* in_sizes, int n_in,
                              void* d_out, int out_size) {
    const float* x    = (const float*)d_in[0];
    const float* Wih0 = (const float*)d_in[1];
    const float* Whh0 = (const float*)d_in[2];
    const float* bih0 = (const float*)d_in[3];
    const float* bhh0 = (const float*)d_in[4];
    const float* WihS = (const float*)d_in[5];
    const float* WhhS = (const float*)d_in[6];
    const float* bihS = (const float*)d_in[7];
    const float* bhhS = (const float*)d_in[8];
    float* out = (float*)d_out;

    float *xgP, *actA, *actB;
    __nv_bfloat16 *AbigP, *WbigP, *WhhBigP;
    cudaGetSymbolAddress((void**)&xgP, g_xg);
    cudaGetSymbolAddress((void**)&actA, g_actA);
    cudaGetSymbolAddress((void**)&actB, g_actB);
    cudaGetSymbolAddress((void**)&AbigP, g_Abig);
    cudaGetSymbolAddress((void**)&WbigP, g_Wbig);
    cudaGetSymbolAddress((void**)&WhhBigP, g_WhhBig);

    cudaFuncSetAttribute(gemm_tc, cudaFuncAttributeMaxDynamicSharedMemorySize,
                         (int)GEMM_SMEM);
    cudaFuncSetAttribute(gru_rec_tc, cudaFuncAttributeMaxDynamicSharedMemorySize,
                         (int)SM_REC_TOTAL);

    const int nblk = (G_DIM * H_DIM + 255) / 256;
    auto wih_of = [&](int l) { return (l == 0) ? Wih0 : WihS + (size_t)(l - 1) * G_DIM * H_DIM; };
    auto whh_of = [&](int l) { return (l == 0) ? Whh0 : WhhS + (size_t)(l - 1) * G_DIM * H_DIM; };

    // ncu alignment: [0] split_l0 [1] split_x0 [2] gemm0 [3] rec0 (capture slot)
    split_l0<<<2 * nblk, 256>>>(Wih0, Whh0, WbigP, WhhBigP);

    for (int l = 0; l < 4; ++l) {
        const float* bih = (l == 0) ? bih0 : bihS + (size_t)(l - 1) * G_DIM;
        const float* bhh = (l == 0) ? bhh0 : bhhS + (size_t)(l - 1) * G_DIM;

        const float* ain = (l & 1) ? actB : actA;
        float* aout = (l == 3) ? out : ((l & 1) ? actA : actB);

        if (l == 0)
            split_x0<<<T_STEPS, 256>>>(x, AbigP);
        else
            split_act<<<dim3(T_STEPS, H_DIM / 64), 256>>>(ain, AbigP);

        gemm_tc<<<dim3(G_DIM / 128, M_BIG / 128), 256, GEMM_SMEM>>>(
            AbigP, WbigP + (size_t)l * G_DIM * K2, bih, xgP);

        gru_rec_tc<<<RCTAS, RTHR, SM_REC_TOTAL>>>(
            WhhBigP + (size_t)l * G_DIM * KBIG, bhh, xgP,
            (l == 0) ? nullptr : ain, aout, (l == 3) ? 1 : 0,
            l * (T_STEPS + 1));

        if (l < 3) {
            split_w2<<<nblk, 256>>>(wih_of(l + 1), WbigP + (size_t)(l + 1) * G_DIM * K2);
            split_w<<<nblk, 256>>>(whh_of(l + 1), WhhBigP + (size_t)(l + 1) * G_DIM * KBIG);
        }
    }
}

// round 12
// speedup vs baseline: 1.0759x; 1.0759x over previous
#include <cuda_runtime.h>
#include <cuda_bf16.h>
#include <cstdint>

#define T_STEPS 1024
#define H_DIM   768
#define B_DIM   32
#define G_DIM   (3*H_DIM)     // 2304
#define K2      1536          // [hi|lo] packed K for GEMM
#define KBIG    2304          // 3-term K for recurrent W_hh
#define M_BIG   (T_STEPS*B_DIM) // 32768

// ---------------- static device scratch ----------------
__device__ float g_xg[(size_t)T_STEPS * G_DIM * B_DIM];
__device__ float g_actA[(size_t)T_STEPS * H_DIM * B_DIM];
__device__ float g_actB[(size_t)T_STEPS * H_DIM * B_DIM];
__device__ __align__(1024) __nv_bfloat16 g_Abig[(size_t)M_BIG * K2];
__device__ __align__(1024) __nv_bfloat16 g_Wbig[(size_t)4 * G_DIM * K2];
__device__ __align__(1024) __nv_bfloat16 g_WhhBig[(size_t)4 * G_DIM * KBIG];
// h ping-pong, stored in SWIZZLED CHUNK ORDER (see hs_chunk): 96KB each
__device__ __align__(1024) char g_hs[2][1536 * B_DIM * 2];
__device__ unsigned int g_arrive = 0;
__device__ volatile unsigned int g_gen = 0;

// ---------------- bf16 two-term split helpers ----------------
__device__ __forceinline__ void split_bf16(float v, __nv_bfloat16& hi, __nv_bfloat16& lo) {
    hi = __float2bfloat16(v);
    lo = __float2bfloat16(v - __bfloat162float(hi));
}
__device__ __forceinline__ float fast_sigmoid(float x) {
    return __fdividef(1.f, 1.f + __expf(-x));
}
__device__ __forceinline__ float fast_tanh(float x) {
    return 2.f * __fdividef(1.f, 1.f + __expf(-2.f * x)) - 1.f;
}

// swizzled 16B-chunk index for h: row k (64B = 4 chunks), chunk c
__device__ __forceinline__ uint32_t hs_chunk(int k, int c) {
    return (uint32_t)((k >> 1) * 8 + ((((k & 1) << 2) | c) ^ ((k >> 1) & 7)));
}
// byte offset of element (k, b) in the swizzled layout
__device__ __forceinline__ size_t hs_goff(int k, int b) {
    return (size_t)hs_chunk(k, b >> 3) * 16 + (size_t)(b & 7) * 2;
}

// ---------------- split kernels ----------------
__global__ void __launch_bounds__(256) split_x0(const float* __restrict__ x,
                                                __nv_bfloat16* __restrict__ Ab) {
    int t = blockIdx.x;
    for (int i = threadIdx.x; i < 32 * H_DIM; i += 256) {
        int b = i / H_DIM, d = i % H_DIM;
        float v = x[((size_t)b * T_STEPS + t) * H_DIM + d];
        __nv_bfloat16 hi, lo; split_bf16(v, hi, lo);
        size_t r = ((size_t)t * 32 + b) * K2;
        Ab[r + d] = hi;
        Ab[r + 768 + d] = lo;
    }
}

__global__ void __launch_bounds__(256) split_act(const float* __restrict__ act,
                                                 __nv_bfloat16* __restrict__ Ab) {
    __shared__ float sm[64][33];
    int t = blockIdx.x;
    int d0 = blockIdx.y * 64;
    int ts = T_STEPS - 1 - t;
    for (int i = threadIdx.x; i < 64 * 32; i += 256) {
        int dl = i >> 5, b = i & 31;
        sm[dl][b] = act[((size_t)ts * H_DIM + d0 + dl) * B_DIM + b];
    }
    __syncthreads();
    for (int i = threadIdx.x; i < 32 * 64; i += 256) {
        int b = i >> 6, dl = i & 63;
        float v = sm[dl][b];
        __nv_bfloat16 hi, lo; split_bf16(v, hi, lo);
        size_t r = ((size_t)t * 32 + b) * K2;
        Ab[r + d0 + dl] = hi;
        Ab[r + 768 + d0 + dl] = lo;
    }
}

__global__ void __launch_bounds__(256) split_w2(const float* __restrict__ W,
                                                __nv_bfloat16* __restrict__ Wb) {
    int i = blockIdx.x * 256 + threadIdx.x;
    if (i >= G_DIM * H_DIM) return;
    int g = i / H_DIM, d = i % H_DIM;
    float v = W[i];
    __nv_bfloat16 hi, lo; split_bf16(v, hi, lo);
    size_t r = (size_t)g * K2;
    Wb[r + d] = hi;
    Wb[r + 768 + d] = lo;
}

__global__ void __launch_bounds__(256) split_w(const float* __restrict__ W,
                                               __nv_bfloat16* __restrict__ Wb) {
    int i = blockIdx.x * 256 + threadIdx.x;
    if (i >= G_DIM * H_DIM) return;
    int g = i / H_DIM, d = i % H_DIM;
    float v = W[i];
    __nv_bfloat16 hi, lo; split_bf16(v, hi, lo);
    size_t r = (size_t)g * KBIG;
    Wb[r + d] = hi;
    Wb[r + 768 + d] = hi;
    Wb[r + 1536 + d] = lo;
}

__global__ void __launch_bounds__(256) split_l0(const float* __restrict__ Wih0,
                                                const float* __restrict__ Whh0,
                                                __nv_bfloat16* __restrict__ Wb,
                                                __nv_bfloat16* __restrict__ Whh) {
    int half = gridDim.x >> 1;
    if (blockIdx.x < half) {
        int i = blockIdx.x * 256 + threadIdx.x;
        if (i >= G_DIM * H_DIM) return;
        int g = i / H_DIM, d = i % H_DIM;
        float v = Wih0[i];
        __nv_bfloat16 hi, lo; split_bf16(v, hi, lo);
        size_t r = (size_t)g * K2;
        Wb[r + d] = hi;
        Wb[r + 768 + d] = lo;
    } else {
        int i = (blockIdx.x - half) * 256 + threadIdx.x;
        if (i >= G_DIM * H_DIM) return;
        int g = i / H_DIM, d = i % H_DIM;
        float v = Whh0[i];
        __nv_bfloat16 hi, lo; split_bf16(v, hi, lo);
        size_t r = (size_t)g * KBIG;
        Whh[r + d] = hi;
        Whh[r + 768 + d] = hi;
        Whh[r + 1536 + d] = lo;
    }
}

// ---------------- common asm helpers ----------------
__device__ __forceinline__ void cp16(void* s, const void* g) {
    uint32_t sa = (uint32_t)__cvta_generic_to_shared(s);
    asm volatile("cp.async.cg.shared.global [%0], [%1], 16;\n" :: "r"(sa), "l"(g));
}
__device__ __forceinline__ void ldsm_x4(uint32_t& r0, uint32_t& r1, uint32_t& r2, uint32_t& r3,
                                        const __nv_bfloat16* p) {
    uint32_t a = (uint32_t)__cvta_generic_to_shared(p);
    asm volatile("ldmatrix.sync.aligned.m8n8.x4.shared.b16 {%0,%1,%2,%3}, [%4];\n"
                 : "=r"(r0), "=r"(r1), "=r"(r2), "=r"(r3) : "r"(a));
}
__device__ __forceinline__ void ldsm_x4a(uint32_t& r0, uint32_t& r1, uint32_t& r2, uint32_t& r3,
                                         uint32_t a) {
    asm volatile("ldmatrix.sync.aligned.m8n8.x4.shared.b16 {%0,%1,%2,%3}, [%4];\n"
                 : "=r"(r0), "=r"(r1), "=r"(r2), "=r"(r3) : "r"(a));
}
__device__ __forceinline__ void ldsm_x4t(uint32_t& r0, uint32_t& r1, uint32_t& r2, uint32_t& r3,
                                         uint32_t a) {
    asm volatile("ldmatrix.sync.aligned.m8n8.x4.trans.shared.b16 {%0,%1,%2,%3}, [%4];\n"
                 : "=r"(r0), "=r"(r1), "=r"(r2), "=r"(r3) : "r"(a));
}
__device__ __forceinline__ void mma_bf16(float* c, const uint32_t* a, const uint32_t* b) {
    asm volatile("mma.sync.aligned.m16n8k16.row.col.f32.bf16.bf16.f32 "
                 "{%0,%1,%2,%3}, {%4,%5,%6,%7}, {%8,%9}, {%0,%1,%2,%3};\n"
                 : "+f"(c[0]), "+f"(c[1]), "+f"(c[2]), "+f"(c[3])
                 : "r"(a[0]), "r"(a[1]), "r"(a[2]), "r"(a[3]), "r"(b[0]), "r"(b[1]));
}
// bulk async copy global->shared with mbarrier completion
__device__ __forceinline__ void bulk_cp(uint32_t sdst, const void* gsrc,
                                        uint32_t bytes, uint32_t mbar) {
    asm volatile(
        "cp.async.bulk.shared::cluster.global.mbarrier::complete_tx::bytes [%0], [%1], %2, [%3];\n"
        :: "r"(sdst), "l"(gsrc), "r"(bytes), "r"(mbar) : "memory");
}
__device__ __forceinline__ void mbar_init1(uint32_t mbar) {
    asm volatile("mbarrier.init.shared.b64 [%0], 1;\n" :: "r"(mbar) : "memory");
}
__device__ __forceinline__ void mbar_expect_tx(uint32_t mbar, uint32_t bytes) {
    asm volatile("mbarrier.arrive.expect_tx.shared.b64 _, [%0], %1;\n"
                 :: "r"(mbar), "r"(bytes) : "memory");
}
__device__ __forceinline__ void mbar_wait_parity(uint32_t mbar, uint32_t parity) {
    uint32_t done;
    asm volatile(
        "{\n\t.reg .pred p;\n\t"
        "mbarrier.try_wait.parity.acquire.cta.shared::cta.b64 p, [%1], %2;\n\t"
        "selp.b32 %0, 1, 0, p;\n\t}"
        : "=r"(done) : "r"(mbar), "r"(parity) : "memory");
    if (!done) {
        asm volatile(
            "{\n\t.reg .pred P1;\n\t"
            "WL%=:\n\t"
            "mbarrier.try_wait.parity.acquire.cta.shared::cta.b64 P1, [%0], %1, 0x989680;\n\t"
            "@P1 bra.uni WD%=;\n\t"
            "bra.uni WL%=;\n\t"
            "WD%=:\n\t}"
            :: "r"(mbar), "r"(parity) : "memory");
    }
}

// ---------------- input-projection GEMM (unchanged, best-measured) ----------------
#define SPITCH 40
#define T1 (128 * SPITCH)
#define STG2 (4 * T1)
#define GITER 24

__global__ void __launch_bounds__(256, 1) gemm_tc(
    const __nv_bfloat16* __restrict__ A,
    const __nv_bfloat16* __restrict__ Wb,
    const float* __restrict__ bias,
    float* __restrict__ xg)
{
    extern __shared__ char smem_raw[];
    __nv_bfloat16* sm = (__nv_bfloat16*)smem_raw;

    const int tid = threadIdx.x;
    const int lane = tid & 31;
    const int warp = tid >> 5;
    const int wm = warp >> 1;
    const int wn = warp & 1;
    const int gBase = blockIdx.x * 128;
    const int mBase = blockIdx.y * 128;

    float acc[2][8][4];
#pragma unroll
    for (int i = 0; i < 2; ++i)
#pragma unroll
        for (int j = 0; j < 8; ++j)
#pragma unroll
            for (int k = 0; k < 4; ++k) acc[i][j][k] = 0.f;

    auto load_tile = [&](int stage, int it) {
        __nv_bfloat16* base = sm + stage * STG2;
        int k0 = it * 32;
        int c = tid & 3;
        int rhalf = tid >> 2;
#pragma unroll
        for (int j = 0; j < 8; ++j) {
            int tile = j >> 1;
            int row = (j & 1) * 64 + rhalf;
            const __nv_bfloat16* src =
                (tile < 2 ? A + (size_t)(mBase + row) * K2
                          : Wb + (size_t)(gBase + row) * K2)
                + (tile & 1) * 768 + k0 + c * 8;
            cp16(base + tile * T1 + row * SPITCH + c * 8, src);
        }
    };

#pragma unroll
    for (int s = 0; s < 3; ++s) {
        load_tile(s, s);
        asm volatile("cp.async.commit_group;\n" ::: "memory");
    }

    for (int it = 0; it < GITER; ++it) {
        asm volatile("cp.async.wait_group %0;\n" :: "n"(2) : "memory");
        __syncthreads();
        int itn = it + 3;
        if (itn < GITER) load_tile(itn & 3, itn);
        asm volatile("cp.async.commit_group;\n" ::: "memory");

        const __nv_bfloat16* Ah = sm + (it & 3) * STG2;
        const __nv_bfloat16* Al = Ah + T1;
        const __nv_bfloat16* Wh = Ah + 2 * T1;
        const __nv_bfloat16* Wl = Ah + 3 * T1;
#pragma unroll
        for (int kk = 0; kk < 2; ++kk) {
            uint32_t afh[2][4], afl[2][4];
            uint32_t bfh[8][2], bfl[8][2];
#pragma unroll
            for (int mt = 0; mt < 2; ++mt) {
                int ro = (wm * 32 + mt * 16 + (lane & 15)) * SPITCH + kk * 16 + (lane >> 4) * 8;
                ldsm_x4(afh[mt][0], afh[mt][1], afh[mt][2], afh[mt][3], Ah + ro);
                ldsm_x4(afl[mt][0], afl[mt][1], afl[mt][2], afl[mt][3], Al + ro);
            }
#pragma unroll
            for (int np = 0; np < 4; ++np) {
                int grp = lane >> 3;
                int ro = (wn * 64 + np * 16 + (grp >> 1) * 8 + (lane & 7)) * SPITCH
                       + kk * 16 + (grp & 1) * 8;
                uint32_t r0, r1, r2, r3;
                ldsm_x4(r0, r1, r2, r3, Wh + ro);
                bfh[2 * np][0] = r0; bfh[2 * np][1] = r1;
                bfh[2 * np + 1][0] = r2; bfh[2 * np + 1][1] = r3;
                ldsm_x4(r0, r1, r2, r3, Wl + ro);
                bfl[2 * np][0] = r0; bfl[2 * np][1] = r1;
                bfl[2 * np + 1][0] = r2; bfl[2 * np + 1][1] = r3;
            }
#pragma unroll
            for (int mt = 0; mt < 2; ++mt)
#pragma unroll
                for (int nt = 0; nt < 8; ++nt) {
                    mma_bf16(acc[mt][nt], afh[mt], bfh[nt]);
                    mma_bf16(acc[mt][nt], afl[mt], bfh[nt]);
                    mma_bf16(acc[mt][nt], afh[mt], bfl[nt]);
                }
        }
    }
    asm volatile("cp.async.wait_all;\n" ::: "memory");
    __syncthreads();

    float* ebuf = (float*)smem_raw + warp * (64 * 33);
#pragma unroll
    for (int mt = 0; mt < 2; ++mt)
#pragma unroll
        for (int nt = 0; nt < 8; ++nt) {
            int b0 = mt * 16 + (lane >> 2);
            int gl = nt * 8 + (lane & 3) * 2;
            ebuf[gl * 33 + b0]            = acc[mt][nt][0];
            ebuf[(gl + 1) * 33 + b0]      = acc[mt][nt][1];
            ebuf[gl * 33 + b0 + 8]        = acc[mt][nt][2];
            ebuf[(gl + 1) * 33 + b0 + 8]  = acc[mt][nt][3];
        }
    __syncwarp();
    int t = blockIdx.y * 4 + wm;
    int g0 = gBase + wn * 64;
    size_t obase = (size_t)t * (G_DIM * B_DIM);
#pragma unroll 4
    for (int g = 0; g < 64; ++g) {
        xg[obase + (size_t)(g0 + g) * B_DIM + lane] = ebuf[g * 33 + lane] + bias[g0 + g];
    }
}
#define GEMM_SMEM ((4 * STG2 * 2 > 8 * 64 * 33 * 4) ? 4 * STG2 * 2 : 8 * 64 * 33 * 4)

// ================= tensor-core recurrent kernel (bulk-copy staging) =================
#define RCTAS 96
#define RTHR  384
#define WPITCH 2312
#define SM_W_BYTES (24 * WPITCH * 2)     // 110976
#define SM_H_OFF   SM_W_BYTES
#define SM_H_BYTES (1536 * 64)           // 98304 (48KB hi + 48KB lo)
#define SM_H_HALF  (SM_H_BYTES / 2)      // 49152
#define SM_PART_OFF (SM_H_OFF + SM_H_BYTES)
#define SM_PART_BYTES (12 * 2 * 4 * 32 * 4)
#define SM_BSH_OFF (SM_PART_OFF + SM_PART_BYTES)
#define SM_MBAR_OFF (SM_BSH_OFF + 96)    // two 8B mbarriers in the pad
#define SM_REC_TOTAL (SM_BSH_OFF + 128)

__global__ void __launch_bounds__(RTHR, 1) gru_rec_tc(
    const __nv_bfloat16* __restrict__ WhhB,
    const float* __restrict__ bhh,
    const float* __restrict__ xg,
    const float* __restrict__ res,
    float* __restrict__ out,
    int out_mode)
{
    extern __shared__ __align__(1024) char smr[];
    __nv_bfloat16* Wsm = (__nv_bfloat16*)smr;
    const uint32_t hs_base = (uint32_t)__cvta_generic_to_shared(smr + SM_H_OFF);
    float* part = (float*)(smr + SM_PART_OFF);
    float* bsh  = (float*)(smr + SM_BSH_OFF);
    const uint32_t mb_hi = (uint32_t)__cvta_generic_to_shared(smr + SM_MBAR_OFF);
    const uint32_t mb_lo = mb_hi + 8;

    const int tid = threadIdx.x;
    const int lane = tid & 31;
    const int w = tid >> 5;
    const int kq = w & 3;
    const int nt = w >> 2;
    const int cta = blockIdx.x;

    const int jlf = tid >> 5;
    const int jgf = cta * 8 + jlf;

    // W_hh slice -> smem
#pragma unroll
    for (int i = 0; i < 18; ++i) {
        int task = i * RTHR + tid;
        int n = task / 288, c = task % 288;
        int grow = (n >> 3) * H_DIM + cta * 8 + (n & 7);
        cp16(Wsm + n * WPITCH + c * 8, WhhB + (size_t)grow * KBIG + c * 8);
    }
    if (tid < 24) {
        int gt = tid >> 3, jl = tid & 7;
        bsh[tid] = bhh[gt * H_DIM + cta * 8 + jl];
    }
    // zero own slice of h[0] (swizzled global layout)
    if (tid < 256) {
        *(__nv_bfloat16*)(g_hs[0] + hs_goff(jgf, lane)) = __float2bfloat16(0.f);
        *(__nv_bfloat16*)(g_hs[0] + hs_goff(768 + jgf, lane)) = __float2bfloat16(0.f);
    }
    if (tid == 0) {
        mbar_init1(mb_hi);
        mbar_init1(mb_lo);
        asm volatile("fence.proxy.async.shared::cta;\n" ::: "memory");
    }
    asm volatile("cp.async.commit_group;\n" ::: "memory");
    asm volatile("cp.async.wait_all;\n" ::: "memory");
    __threadfence();   // publish h zeros — proven writer-side protocol

    // step-0 gate-input prefetch (stream-ordered data, safe before barrier)
    float xr = 0.f, xz = 0.f, xn = 0.f, rv = 0.f;
    auto prefetch = [&](int t) {
        if (tid < 256) {
            size_t base = (size_t)t * (G_DIM * B_DIM);
            xr = xg[base + (size_t)(0 * H_DIM + jgf) * B_DIM + lane];
            xz = xg[base + (size_t)(1 * H_DIM + jgf) * B_DIM + lane];
            xn = xg[base + (size_t)(2 * H_DIM + jgf) * B_DIM + lane];
            if (res)
                rv = res[(size_t)(T_STEPS - 1 - t) * (H_DIM * B_DIM) +
                         (size_t)jgf * B_DIM + lane];
        }
    };
    prefetch(0);

    // initial barrier — proven R8 form
    __syncthreads();
    if (tid == 0) {
        unsigned gen = g_gen;
        if (atomicAdd(&g_arrive, 1) == gridDim.x - 1) {
            atomicExch(&g_arrive, 0);
            __threadfence();
            g_gen = gen + 1;
        }
        while (g_gen == gen) { }
        __threadfence();
    }
    __syncthreads();

    const int t4 = lane >> 3, r8 = lane & 7;
    const uint32_t w_base = (uint32_t)__cvta_generic_to_shared(Wsm)
                          + (uint32_t)((nt * 8 + r8) * WPITCH * 2 + t4 * 16);
    const int a_roff = ((t4 >> 1) << 3) + r8;
    const int a_c0 = (t4 & 1);

    auto a_addr = [&](int kt, int mt) -> uint32_t {
        int krow = (kt << 4) + a_roff;          // kt in 0..95 covers all 1536 rows
        int c = mt * 2 + a_c0;
        return hs_base + hs_chunk(krow, c) * 16;
    };

    const int mtF = lane >> 4, m_in = lane & 15;
    const int lane_src = (m_in & 7) * 4 + (jlf >> 1);
    const int regF = (jlf & 1) + 2 * (m_in >> 3);
    float hprev = 0.f;

    for (int t = 0; t < T_STEPS; ++t) {
        // stage h with two bulk copies (hi 48KB, lo 48KB); swizzle pre-baked in global
        const char* hsrc = g_hs[t & 1];
        if (tid == 0) {
            mbar_expect_tx(mb_hi, SM_H_HALF);
            bulk_cp(hs_base, hsrc, SM_H_HALF, mb_hi);
            mbar_expect_tx(mb_lo, SM_H_HALF);
            bulk_cp(hs_base + SM_H_HALF, hsrc + SM_H_HALF, SM_H_HALF, mb_lo);
        }

        float acc0[4] = {0.f, 0.f, 0.f, 0.f};
        float acc1[4] = {0.f, 0.f, 0.f, 0.f};

        auto do_pairAB = [&](int q) {
            uint32_t a0 = a_addr(2 * q, 0);
            uint32_t a1 = a_addr(2 * q, 1);
            uint32_t fA0[4], fA1[4], fB0[4], fB1[4];
            ldsm_x4t(fA0[0], fA0[1], fA0[2], fA0[3], a0);
            ldsm_x4t(fA1[0], fA1[1], fA1[2], fA1[3], a1);
            ldsm_x4t(fB0[0], fB0[1], fB0[2], fB0[3], a0 + 1024);
            ldsm_x4t(fB1[0], fB1[1], fB1[2], fB1[3], a1 + 1024);
            uint32_t b0, b1, b2, b3;
            ldsm_x4a(b0, b1, b2, b3, w_base + (uint32_t)(q * 64));
            { uint32_t bA[2] = {b0, b1}, bB[2] = {b2, b3};
              mma_bf16(acc0, fA0, bA); mma_bf16(acc1, fA1, bA);
              mma_bf16(acc0, fB0, bB); mma_bf16(acc1, fB1, bB); }
            ldsm_x4a(b0, b1, b2, b3, w_base + (uint32_t)((q + 48) * 64));
            { uint32_t bA[2] = {b0, b1}, bB[2] = {b2, b3};
              mma_bf16(acc0, fA0, bA); mma_bf16(acc1, fA1, bA);
              mma_bf16(acc0, fB0, bB); mma_bf16(acc1, fB1, bB); }
        };
        auto do_pair = [&](int q) {
            uint32_t b0, b1, b2, b3;
            ldsm_x4a(b0, b1, b2, b3, w_base + (uint32_t)(q * 64));
            uint32_t bA[2] = {b0, b1}, bB[2] = {b2, b3};
            uint32_t a0 = a_addr(2 * q, 0);
            uint32_t a1 = a_addr(2 * q, 1);
            uint32_t af[4];
            ldsm_x4t(af[0], af[1], af[2], af[3], a0);
            mma_bf16(acc0, af, bA);
            ldsm_x4t(af[0], af[1], af[2], af[3], a1);
            mma_bf16(acc1, af, bA);
            ldsm_x4t(af[0], af[1], af[2], af[3], a0 + 1024);
            mma_bf16(acc0, af, bB);
            ldsm_x4t(af[0], af[1], af[2], af[3], a1 + 1024);
            mma_bf16(acc1, af, bB);
        };

        // phase A: hi rows (q<24 => kt<48 => rows<768)
        mbar_wait_parity(mb_hi, (uint32_t)(t & 1));
#pragma unroll
        for (int p = 0; p < 6; ++p) do_pairAB(kq + 4 * p);

        // phase B: lo rows (q in 24..47 => rows 768..1535)
        mbar_wait_parity(mb_lo, (uint32_t)(t & 1));
#pragma unroll
        for (int p = 0; p < 6; ++p) do_pair(24 + kq + 4 * p);

#pragma unroll
        for (int rg = 0; rg < 4; ++rg) {
            part[((w * 2 + 0) * 4 + rg) * 32 + lane] = acc0[rg];
            part[((w * 2 + 1) * 4 + rg) * 32 + lane] = acc1[rg];
        }
        __syncthreads();

        // finalize — proven R8 form (h store + out store + per-writer fence)
        if (tid < 256) {
            float g3[3];
#pragma unroll
            for (int gt = 0; gt < 3; ++gt) {
                float s = 0.f;
#pragma unroll
                for (int k4 = 0; k4 < 4; ++k4) {
                    int wsrc = gt * 4 + k4;
                    s += part[((wsrc * 2 + mtF) * 4 + regF) * 32 + lane_src];
                }
                g3[gt] = s + bsh[gt * 8 + jlf];
            }
            float r = fast_sigmoid(xr + g3[0]);
            float z = fast_sigmoid(xz + g3[1]);
            float n = fast_tanh(xn + r * g3[2]);
            float hv = (1.f - z) * n + z * hprev;
            hprev = hv;
            __nv_bfloat16 hi, lo; split_bf16(hv, hi, lo);
            char* hdst = g_hs[(t & 1) ^ 1];
            *(__nv_bfloat16*)(hdst + hs_goff(jgf, lane)) = hi;
            *(__nv_bfloat16*)(hdst + hs_goff(768 + jgf, lane)) = lo;
            float ov = rv + hv;
            if (out_mode == 0)
                out[(size_t)t * (H_DIM * B_DIM) + (size_t)jgf * B_DIM + lane] = ov;
            else
                out[((size_t)lane * T_STEPS + (T_STEPS - 1 - t)) * H_DIM + jgf] = ov;
            __threadfence();
        }

        // split barrier: sync -> arrive -> prefetch window -> spin -> sync (R8 form)
        __syncthreads();
        unsigned gen = 0;
        if (tid == 0) {
            gen = g_gen;
            if (atomicAdd(&g_arrive, 1) == gridDim.x - 1) {
                atomicExch(&g_arrive, 0);
                __threadfence();
                g_gen = gen + 1;
            }
        }
        if (t + 1 < T_STEPS) prefetch(t + 1);
        if (tid == 0) {
            while (g_gen == gen) { }
            __threadfence();
        }
        __syncthreads();
    }
}

// ---------------- host launcher ----------------
extern "C" void kernel_launch(void* const* d_in, const int* in_sizes, int n_in,
                              void* d_out, int out_size) {
    const float* x    = (const float*)d_in[0];
    const float* Wih0 = (const float*)d_in[1];
    const float* Whh0 = (const float*)d_in[2];
    const float* bih0 = (const float*)d_in[3];
    const float* bhh0 = (const float*)d_in[4];
    const float* WihS = (const float*)d_in[5];
    const float* WhhS = (const float*)d_in[6];
    const float* bihS = (const float*)d_in[7];
    const float* bhhS = (const float*)d_in[8];
    float* out = (float*)d_out;

    float *xgP, *actA, *actB;
    __nv_bfloat16 *AbigP, *WbigP, *WhhBigP;
    cudaGetSymbolAddress((void**)&xgP, g_xg);
    cudaGetSymbolAddress((void**)&actA, g_actA);
    cudaGetSymbolAddress((void**)&actB, g_actB);
    cudaGetSymbolAddress((void**)&AbigP, g_Abig);
    cudaGetSymbolAddress((void**)&WbigP, g_Wbig);
    cudaGetSymbolAddress((void**)&WhhBigP, g_WhhBig);

    cudaFuncSetAttribute(gemm_tc, cudaFuncAttributeMaxDynamicSharedMemorySize,
                         (int)GEMM_SMEM);
    cudaFuncSetAttribute(gru_rec_tc, cudaFuncAttributeMaxDynamicSharedMemorySize,
                         (int)SM_REC_TOTAL);

    const int nblk = (G_DIM * H_DIM + 255) / 256;
    auto wih_of = [&](int l) { return (l == 0) ? Wih0 : WihS + (size_t)(l - 1) * G_DIM * H_DIM; };
    auto whh_of = [&](int l) { return (l == 0) ? Whh0 : WhhS + (size_t)(l - 1) * G_DIM * H_DIM; };

    // ncu alignment: [0] split_l0 [1] split_x0 [2] gemm0 [3] rec0 (capture slot)
    split_l0<<<2 * nblk, 256>>>(Wih0, Whh0, WbigP, WhhBigP);

    for (int l = 0; l < 4; ++l) {
        const float* bih = (l == 0) ? bih0 : bihS + (size_t)(l - 1) * G_DIM;
        const float* bhh = (l == 0) ? bhh0 : bhhS + (size_t)(l - 1) * G_DIM;

        const float* ain = (l & 1) ? actB : actA;
        float* aout = (l == 3) ? out : ((l & 1) ? actA : actB);

        if (l == 0)
            split_x0<<<T_STEPS, 256>>>(x, AbigP);
        else
            split_act<<<dim3(T_STEPS, H_DIM / 64), 256>>>(ain, AbigP);

        gemm_tc<<<dim3(G_DIM / 128, M_BIG / 128), 256, GEMM_SMEM>>>(
            AbigP, WbigP + (size_t)l * G_DIM * K2, bih, xgP);

        gru_rec_tc<<<RCTAS, RTHR, SM_REC_TOTAL>>>(
            WhhBigP + (size_t)l * G_DIM * KBIG, bhh, xgP,
            (l == 0) ? nullptr : ain, aout, (l == 3) ? 1 : 0);

        if (l < 3) {
            split_w2<<<nblk, 256>>>(wih_of(l + 1), WbigP + (size_t)(l + 1) * G_DIM * K2);
            split_w<<<nblk, 256>>>(whh_of(l + 1), WhhBigP + (size_t)(l + 1) * G_DIM * KBIG);
        }
    }
}

// round 13
// speedup vs baseline: 1.0912x; 1.0142x over previous
#include <cuda_runtime.h>
#include <cuda_bf16.h>
#include <cstdint>

#define T_STEPS 1024
#define H_DIM   768
#define B_DIM   32
#define G_DIM   (3*H_DIM)     // 2304
#define K2      1536          // [hi|lo] packed K for GEMM
#define KBIG    2304          // 3-term K for recurrent W_hh
#define M_BIG   (T_STEPS*B_DIM) // 32768

// ---------------- static device scratch ----------------
__device__ float g_xg[(size_t)T_STEPS * G_DIM * B_DIM];
__device__ float g_actA[(size_t)T_STEPS * H_DIM * B_DIM];
__device__ float g_actB[(size_t)T_STEPS * H_DIM * B_DIM];
__device__ __align__(1024) __nv_bfloat16 g_Abig[(size_t)M_BIG * K2];
__device__ __align__(1024) __nv_bfloat16 g_Wbig[(size_t)4 * G_DIM * K2];
__device__ __align__(1024) __nv_bfloat16 g_WhhBig[(size_t)4 * G_DIM * KBIG];
// h ping-pong, stored in SWIZZLED CHUNK ORDER (see hs_chunk): 96KB each
__device__ __align__(1024) char g_hs[2][1536 * B_DIM * 2];
__device__ unsigned int g_arrive = 0;
__device__ volatile unsigned int g_gen = 0;

// ---------------- bf16 two-term split helpers ----------------
__device__ __forceinline__ void split_bf16(float v, __nv_bfloat16& hi, __nv_bfloat16& lo) {
    hi = __float2bfloat16(v);
    lo = __float2bfloat16(v - __bfloat162float(hi));
}
__device__ __forceinline__ float fast_sigmoid(float x) {
    return __fdividef(1.f, 1.f + __expf(-x));
}
__device__ __forceinline__ float fast_tanh(float x) {
    return 2.f * __fdividef(1.f, 1.f + __expf(-2.f * x)) - 1.f;
}

// swizzled 16B-chunk index for h: row k (64B = 4 chunks), chunk c
__device__ __forceinline__ uint32_t hs_chunk(int k, int c) {
    return (uint32_t)((k >> 1) * 8 + ((((k & 1) << 2) | c) ^ ((k >> 1) & 7)));
}
__device__ __forceinline__ size_t hs_goff(int k, int b) {
    return (size_t)hs_chunk(k, b >> 3) * 16 + (size_t)(b & 7) * 2;
}

// ---------------- split kernels ----------------
__global__ void __launch_bounds__(256) split_x0(const float* __restrict__ x,
                                                __nv_bfloat16* __restrict__ Ab) {
    int t = blockIdx.x;
    for (int i = threadIdx.x; i < 32 * H_DIM; i += 256) {
        int b = i / H_DIM, d = i % H_DIM;
        float v = x[((size_t)b * T_STEPS + t) * H_DIM + d];
        __nv_bfloat16 hi, lo; split_bf16(v, hi, lo);
        size_t r = ((size_t)t * 32 + b) * K2;
        Ab[r + d] = hi;
        Ab[r + 768 + d] = lo;
    }
}

__global__ void __launch_bounds__(256) split_act(const float* __restrict__ act,
                                                 __nv_bfloat16* __restrict__ Ab) {
    __shared__ float sm[64][33];
    int t = blockIdx.x;
    int d0 = blockIdx.y * 64;
    int ts = T_STEPS - 1 - t;
    for (int i = threadIdx.x; i < 64 * 32; i += 256) {
        int dl = i >> 5, b = i & 31;
        sm[dl][b] = act[((size_t)ts * H_DIM + d0 + dl) * B_DIM + b];
    }
    __syncthreads();
    for (int i = threadIdx.x; i < 32 * 64; i += 256) {
        int b = i >> 6, dl = i & 63;
        float v = sm[dl][b];
        __nv_bfloat16 hi, lo; split_bf16(v, hi, lo);
        size_t r = ((size_t)t * 32 + b) * K2;
        Ab[r + d0 + dl] = hi;
        Ab[r + 768 + d0 + dl] = lo;
    }
}

__global__ void __launch_bounds__(256) split_w2(const float* __restrict__ W,
                                                __nv_bfloat16* __restrict__ Wb) {
    int i = blockIdx.x * 256 + threadIdx.x;
    if (i >= G_DIM * H_DIM) return;
    int g = i / H_DIM, d = i % H_DIM;
    float v = W[i];
    __nv_bfloat16 hi, lo; split_bf16(v, hi, lo);
    size_t r = (size_t)g * K2;
    Wb[r + d] = hi;
    Wb[r + 768 + d] = lo;
}

__global__ void __launch_bounds__(256) split_w(const float* __restrict__ W,
                                               __nv_bfloat16* __restrict__ Wb) {
    int i = blockIdx.x * 256 + threadIdx.x;
    if (i >= G_DIM * H_DIM) return;
    int g = i / H_DIM, d = i % H_DIM;
    float v = W[i];
    __nv_bfloat16 hi, lo; split_bf16(v, hi, lo);
    size_t r = (size_t)g * KBIG;
    Wb[r + d] = hi;
    Wb[r + 768 + d] = hi;
    Wb[r + 1536 + d] = lo;
}

__global__ void __launch_bounds__(256) split_l0(const float* __restrict__ Wih0,
                                                const float* __restrict__ Whh0,
                                                __nv_bfloat16* __restrict__ Wb,
                                                __nv_bfloat16* __restrict__ Whh) {
    int half = gridDim.x >> 1;
    if (blockIdx.x < half) {
        int i = blockIdx.x * 256 + threadIdx.x;
        if (i >= G_DIM * H_DIM) return;
        int g = i / H_DIM, d = i % H_DIM;
        float v = Wih0[i];
        __nv_bfloat16 hi, lo; split_bf16(v, hi, lo);
        size_t r = (size_t)g * K2;
        Wb[r + d] = hi;
        Wb[r + 768 + d] = lo;
    } else {
        int i = (blockIdx.x - half) * 256 + threadIdx.x;
        if (i >= G_DIM * H_DIM) return;
        int g = i / H_DIM, d = i % H_DIM;
        float v = Whh0[i];
        __nv_bfloat16 hi, lo; split_bf16(v, hi, lo);
        size_t r = (size_t)g * KBIG;
        Whh[r + d] = hi;
        Whh[r + 768 + d] = hi;
        Whh[r + 1536 + d] = lo;
    }
}

// ---------------- common asm helpers ----------------
__device__ __forceinline__ void cp16(void* s, const void* g) {
    uint32_t sa = (uint32_t)__cvta_generic_to_shared(s);
    asm volatile("cp.async.cg.shared.global [%0], [%1], 16;\n" :: "r"(sa), "l"(g));
}
__device__ __forceinline__ void ldsm_x4(uint32_t& r0, uint32_t& r1, uint32_t& r2, uint32_t& r3,
                                        const __nv_bfloat16* p) {
    uint32_t a = (uint32_t)__cvta_generic_to_shared(p);
    asm volatile("ldmatrix.sync.aligned.m8n8.x4.shared.b16 {%0,%1,%2,%3}, [%4];\n"
                 : "=r"(r0), "=r"(r1), "=r"(r2), "=r"(r3) : "r"(a));
}
__device__ __forceinline__ void ldsm_x4a(uint32_t& r0, uint32_t& r1, uint32_t& r2, uint32_t& r3,
                                         uint32_t a) {
    asm volatile("ldmatrix.sync.aligned.m8n8.x4.shared.b16 {%0,%1,%2,%3}, [%4];\n"
                 : "=r"(r0), "=r"(r1), "=r"(r2), "=r"(r3) : "r"(a));
}
__device__ __forceinline__ void ldsm_x4t(uint32_t& r0, uint32_t& r1, uint32_t& r2, uint32_t& r3,
                                         uint32_t a) {
    asm volatile("ldmatrix.sync.aligned.m8n8.x4.trans.shared.b16 {%0,%1,%2,%3}, [%4];\n"
                 : "=r"(r0), "=r"(r1), "=r"(r2), "=r"(r3) : "r"(a));
}
__device__ __forceinline__ void mma_bf16(float* c, const uint32_t* a, const uint32_t* b) {
    asm volatile("mma.sync.aligned.m16n8k16.row.col.f32.bf16.bf16.f32 "
                 "{%0,%1,%2,%3}, {%4,%5,%6,%7}, {%8,%9}, {%0,%1,%2,%3};\n"
                 : "+f"(c[0]), "+f"(c[1]), "+f"(c[2]), "+f"(c[3])
                 : "r"(a[0]), "r"(a[1]), "r"(a[2]), "r"(a[3]), "r"(b[0]), "r"(b[1]));
}
// bulk async copy with cluster multicast
__device__ __forceinline__ void bulk_cp_mc(uint32_t sdst, const void* gsrc,
                                           uint32_t bytes, uint32_t mbar, uint16_t mask) {
    asm volatile(
        "cp.async.bulk.shared::cluster.global.mbarrier::complete_tx::bytes.multicast::cluster"
        " [%0], [%1], %2, [%3], %4;\n"
        :: "r"(sdst), "l"(gsrc), "r"(bytes), "r"(mbar), "h"(mask) : "memory");
}
__device__ __forceinline__ void mbar_init1(uint32_t mbar) {
    asm volatile("mbarrier.init.shared.b64 [%0], 1;\n" :: "r"(mbar) : "memory");
}
__device__ __forceinline__ void mbar_expect_tx(uint32_t mbar, uint32_t bytes) {
    asm volatile("mbarrier.arrive.expect_tx.shared.b64 _, [%0], %1;\n"
                 :: "r"(mbar), "r"(bytes) : "memory");
}
__device__ __forceinline__ void mbar_wait_parity(uint32_t mbar, uint32_t parity) {
    uint32_t done;
    asm volatile(
        "{\n\t.reg .pred p;\n\t"
        "mbarrier.try_wait.parity.acquire.cta.shared::cta.b64 p, [%1], %2;\n\t"
        "selp.b32 %0, 1, 0, p;\n\t}"
        : "=r"(done) : "r"(mbar), "r"(parity) : "memory");
    if (!done) {
        asm volatile(
            "{\n\t.reg .pred P1;\n\t"
            "WL%=:\n\t"
            "mbarrier.try_wait.parity.acquire.cta.shared::cta.b64 P1, [%0], %1, 0x989680;\n\t"
            "@P1 bra.uni WD%=;\n\t"
            "bra.uni WL%=;\n\t"
            "WD%=:\n\t}"
            :: "r"(mbar), "r"(parity) : "memory");
    }
}
__device__ __forceinline__ uint32_t cluster_rank() {
    uint32_t r;
    asm("mov.u32 %0, %%cluster_ctarank;" : "=r"(r));
    return r;
}

// ---------------- input-projection GEMM (unchanged, best-measured) ----------------
#define SPITCH 40
#define T1 (128 * SPITCH)
#define STG2 (4 * T1)
#define GITER 24

__global__ void __launch_bounds__(256, 1) gemm_tc(
    const __nv_bfloat16* __restrict__ A,
    const __nv_bfloat16* __restrict__ Wb,
    const float* __restrict__ bias,
    float* __restrict__ xg)
{
    extern __shared__ char smem_raw[];
    __nv_bfloat16* sm = (__nv_bfloat16*)smem_raw;

    const int tid = threadIdx.x;
    const int lane = tid & 31;
    const int warp = tid >> 5;
    const int wm = warp >> 1;
    const int wn = warp & 1;
    const int gBase = blockIdx.x * 128;
    const int mBase = blockIdx.y * 128;

    float acc[2][8][4];
#pragma unroll
    for (int i = 0; i < 2; ++i)
#pragma unroll
        for (int j = 0; j < 8; ++j)
#pragma unroll
            for (int k = 0; k < 4; ++k) acc[i][j][k] = 0.f;

    auto load_tile = [&](int stage, int it) {
        __nv_bfloat16* base = sm + stage * STG2;
        int k0 = it * 32;
        int c = tid & 3;
        int rhalf = tid >> 2;
#pragma unroll
        for (int j = 0; j < 8; ++j) {
            int tile = j >> 1;
            int row = (j & 1) * 64 + rhalf;
            const __nv_bfloat16* src =
                (tile < 2 ? A + (size_t)(mBase + row) * K2
                          : Wb + (size_t)(gBase + row) * K2)
                + (tile & 1) * 768 + k0 + c * 8;
            cp16(base + tile * T1 + row * SPITCH + c * 8, src);
        }
    };

#pragma unroll
    for (int s = 0; s < 3; ++s) {
        load_tile(s, s);
        asm volatile("cp.async.commit_group;\n" ::: "memory");
    }

    for (int it = 0; it < GITER; ++it) {
        asm volatile("cp.async.wait_group %0;\n" :: "n"(2) : "memory");
        __syncthreads();
        int itn = it + 3;
        if (itn < GITER) load_tile(itn & 3, itn);
        asm volatile("cp.async.commit_group;\n" ::: "memory");

        const __nv_bfloat16* Ah = sm + (it & 3) * STG2;
        const __nv_bfloat16* Al = Ah + T1;
        const __nv_bfloat16* Wh = Ah + 2 * T1;
        const __nv_bfloat16* Wl = Ah + 3 * T1;
#pragma unroll
        for (int kk = 0; kk < 2; ++kk) {
            uint32_t afh[2][4], afl[2][4];
            uint32_t bfh[8][2], bfl[8][2];
#pragma unroll
            for (int mt = 0; mt < 2; ++mt) {
                int ro = (wm * 32 + mt * 16 + (lane & 15)) * SPITCH + kk * 16 + (lane >> 4) * 8;
                ldsm_x4(afh[mt][0], afh[mt][1], afh[mt][2], afh[mt][3], Ah + ro);
                ldsm_x4(afl[mt][0], afl[mt][1], afl[mt][2], afl[mt][3], Al + ro);
            }
#pragma unroll
            for (int np = 0; np < 4; ++np) {
                int grp = lane >> 3;
                int ro = (wn * 64 + np * 16 + (grp >> 1) * 8 + (lane & 7)) * SPITCH
                       + kk * 16 + (grp & 1) * 8;
                uint32_t r0, r1, r2, r3;
                ldsm_x4(r0, r1, r2, r3, Wh + ro);
                bfh[2 * np][0] = r0; bfh[2 * np][1] = r1;
                bfh[2 * np + 1][0] = r2; bfh[2 * np + 1][1] = r3;
                ldsm_x4(r0, r1, r2, r3, Wl + ro);
                bfl[2 * np][0] = r0; bfl[2 * np][1] = r1;
                bfl[2 * np + 1][0] = r2; bfl[2 * np + 1][1] = r3;
            }
#pragma unroll
            for (int mt = 0; mt < 2; ++mt)
#pragma unroll
                for (int nt = 0; nt < 8; ++nt) {
                    mma_bf16(acc[mt][nt], afh[mt], bfh[nt]);
                    mma_bf16(acc[mt][nt], afl[mt], bfh[nt]);
                    mma_bf16(acc[mt][nt], afh[mt], bfl[nt]);
                }
        }
    }
    asm volatile("cp.async.wait_all;\n" ::: "memory");
    __syncthreads();

    float* ebuf = (float*)smem_raw + warp * (64 * 33);
#pragma unroll
    for (int mt = 0; mt < 2; ++mt)
#pragma unroll
        for (int nt = 0; nt < 8; ++nt) {
            int b0 = mt * 16 + (lane >> 2);
            int gl = nt * 8 + (lane & 3) * 2;
            ebuf[gl * 33 + b0]            = acc[mt][nt][0];
            ebuf[(gl + 1) * 33 + b0]      = acc[mt][nt][1];
            ebuf[gl * 33 + b0 + 8]        = acc[mt][nt][2];
            ebuf[(gl + 1) * 33 + b0 + 8]  = acc[mt][nt][3];
        }
    __syncwarp();
    int t = blockIdx.y * 4 + wm;
    int g0 = gBase + wn * 64;
    size_t obase = (size_t)t * (G_DIM * B_DIM);
#pragma unroll 4
    for (int g = 0; g < 64; ++g) {
        xg[obase + (size_t)(g0 + g) * B_DIM + lane] = ebuf[g * 33 + lane] + bias[g0 + g];
    }
}
#define GEMM_SMEM ((4 * STG2 * 2 > 8 * 64 * 33 * 4) ? 4 * STG2 * 2 : 8 * 64 * 33 * 4)

// ================= tensor-core recurrent kernel (cluster-multicast staging) =================
#define RCTAS 96
#define RTHR  384
#define CLUSTER_SZ 8
#define WPITCH 2312
#define SM_W_BYTES (24 * WPITCH * 2)     // 110976
#define SM_H_OFF   SM_W_BYTES
#define SM_H_BYTES (1536 * 64)           // 98304 (48KB hi + 48KB lo)
#define SM_H_HALF  (SM_H_BYTES / 2)      // 49152
#define SM_H_SLICE (SM_H_BYTES / CLUSTER_SZ)  // 12288 per cluster rank
#define SM_PART_OFF (SM_H_OFF + SM_H_BYTES)
#define SM_PART_BYTES (12 * 2 * 4 * 32 * 4)
#define SM_BSH_OFF (SM_PART_OFF + SM_PART_BYTES)
#define SM_MBAR_OFF (SM_BSH_OFF + 96)
#define SM_REC_TOTAL (SM_BSH_OFF + 128)

__global__ void __launch_bounds__(RTHR, 1) __cluster_dims__(CLUSTER_SZ, 1, 1)
gru_rec_tc(
    const __nv_bfloat16* __restrict__ WhhB,
    const float* __restrict__ bhh,
    const float* __restrict__ xg,
    const float* __restrict__ res,
    float* __restrict__ out,
    int out_mode)
{
    extern __shared__ __align__(1024) char smr[];
    __nv_bfloat16* Wsm = (__nv_bfloat16*)smr;
    const uint32_t hs_base = (uint32_t)__cvta_generic_to_shared(smr + SM_H_OFF);
    float* part = (float*)(smr + SM_PART_OFF);
    float* bsh  = (float*)(smr + SM_BSH_OFF);
    const uint32_t mb_hi = (uint32_t)__cvta_generic_to_shared(smr + SM_MBAR_OFF);
    const uint32_t mb_lo = mb_hi + 8;

    const int tid = threadIdx.x;
    const int lane = tid & 31;
    const int w = tid >> 5;
    const int kq = w & 3;
    const int nt = w >> 2;
    const int cta = blockIdx.x;
    const uint32_t crank = cluster_rank();

    const int jlf = tid >> 5;
    const int jgf = cta * 8 + jlf;

    // W_hh slice -> smem
#pragma unroll
    for (int i = 0; i < 18; ++i) {
        int task = i * RTHR + tid;
        int n = task / 288, c = task % 288;
        int grow = (n >> 3) * H_DIM + cta * 8 + (n & 7);
        cp16(Wsm + n * WPITCH + c * 8, WhhB + (size_t)grow * KBIG + c * 8);
    }
    if (tid < 24) {
        int gt = tid >> 3, jl = tid & 7;
        bsh[tid] = bhh[gt * H_DIM + cta * 8 + jl];
    }
    if (tid < 256) {
        *(__nv_bfloat16*)(g_hs[0] + hs_goff(jgf, lane)) = __float2bfloat16(0.f);
        *(__nv_bfloat16*)(g_hs[0] + hs_goff(768 + jgf, lane)) = __float2bfloat16(0.f);
    }
    if (tid == 0) {
        mbar_init1(mb_hi);
        mbar_init1(mb_lo);
        asm volatile("fence.proxy.async.shared::cta;\n" ::: "memory");
        // expect for step 0 BEFORE the grid barrier (senders issue only after it)
        mbar_expect_tx(mb_hi, SM_H_HALF);
        mbar_expect_tx(mb_lo, SM_H_HALF);
    }
    asm volatile("cp.async.commit_group;\n" ::: "memory");
    asm volatile("cp.async.wait_all;\n" ::: "memory");
    __threadfence();   // publish h zeros — proven writer-side protocol

    // cluster sync: peers' mbarrier init must be visible before any multicast
    asm volatile("barrier.cluster.arrive.aligned;" ::: "memory");
    asm volatile("barrier.cluster.wait.aligned;" ::: "memory");

    // step-0 gate-input prefetch
    float xr = 0.f, xz = 0.f, xn = 0.f, rv = 0.f;
    auto prefetch = [&](int t) {
        if (tid < 256) {
            size_t base = (size_t)t * (G_DIM * B_DIM);
            xr = xg[base + (size_t)(0 * H_DIM + jgf) * B_DIM + lane];
            xz = xg[base + (size_t)(1 * H_DIM + jgf) * B_DIM + lane];
            xn = xg[base + (size_t)(2 * H_DIM + jgf) * B_DIM + lane];
            if (res)
                rv = res[(size_t)(T_STEPS - 1 - t) * (H_DIM * B_DIM) +
                         (size_t)jgf * B_DIM + lane];
        }
    };
    prefetch(0);

    // initial grid barrier — proven R8 form
    __syncthreads();
    if (tid == 0) {
        unsigned gen = g_gen;
        if (atomicAdd(&g_arrive, 1) == gridDim.x - 1) {
            atomicExch(&g_arrive, 0);
            __threadfence();
            g_gen = gen + 1;
        }
        while (g_gen == gen) { }
        __threadfence();
    }
    __syncthreads();

    const int t4 = lane >> 3, r8 = lane & 7;
    const uint32_t w_base = (uint32_t)__cvta_generic_to_shared(Wsm)
                          + (uint32_t)((nt * 8 + r8) * WPITCH * 2 + t4 * 16);
    const int a_roff = ((t4 >> 1) << 3) + r8;
    const int a_c0 = (t4 & 1);

    auto a_addr = [&](int kt, int mt) -> uint32_t {
        int krow = (kt << 4) + a_roff;
        int c = mt * 2 + a_c0;
        return hs_base + hs_chunk(krow, c) * 16;
    };

    const int mtF = lane >> 4, m_in = lane & 15;
    const int lane_src = (m_in & 7) * 4 + (jlf >> 1);
    const int regF = (jlf & 1) + 2 * (m_in >> 3);
    float hprev = 0.f;

    const uint32_t slice_off = crank * SM_H_SLICE;
    const uint32_t slice_mbar = (crank < 4) ? mb_hi : mb_lo;

    for (int t = 0; t < T_STEPS; ++t) {
        // stage h: this CTA multicasts its 12KB slice to all 8 cluster CTAs
        const char* hsrc = g_hs[t & 1];
        if (tid == 0) {
            bulk_cp_mc(hs_base + slice_off, hsrc + slice_off, SM_H_SLICE,
                       slice_mbar, (uint16_t)0xFF);
        }

        float acc0[4] = {0.f, 0.f, 0.f, 0.f};
        float acc1[4] = {0.f, 0.f, 0.f, 0.f};

        auto do_pairAB = [&](int q) {
            uint32_t a0 = a_addr(2 * q, 0);
            uint32_t a1 = a_addr(2 * q, 1);
            uint32_t fA0[4], fA1[4], fB0[4], fB1[4];
            ldsm_x4t(fA0[0], fA0[1], fA0[2], fA0[3], a0);
            ldsm_x4t(fA1[0], fA1[1], fA1[2], fA1[3], a1);
            ldsm_x4t(fB0[0], fB0[1], fB0[2], fB0[3], a0 + 1024);
            ldsm_x4t(fB1[0], fB1[1], fB1[2], fB1[3], a1 + 1024);
            uint32_t b0, b1, b2, b3;
            ldsm_x4a(b0, b1, b2, b3, w_base + (uint32_t)(q * 64));
            { uint32_t bA[2] = {b0, b1}, bB[2] = {b2, b3};
              mma_bf16(acc0, fA0, bA); mma_bf16(acc1, fA1, bA);
              mma_bf16(acc0, fB0, bB); mma_bf16(acc1, fB1, bB); }
            ldsm_x4a(b0, b1, b2, b3, w_base + (uint32_t)((q + 48) * 64));
            { uint32_t bA[2] = {b0, b1}, bB[2] = {b2, b3};
              mma_bf16(acc0, fA0, bA); mma_bf16(acc1, fA1, bA);
              mma_bf16(acc0, fB0, bB); mma_bf16(acc1, fB1, bB); }
        };
        auto do_pair = [&](int q) {
            uint32_t b0, b1, b2, b3;
            ldsm_x4a(b0, b1, b2, b3, w_base + (uint32_t)(q * 64));
            uint32_t bA[2] = {b0, b1}, bB[2] = {b2, b3};
            uint32_t a0 = a_addr(2 * q, 0);
            uint32_t a1 = a_addr(2 * q, 1);
            uint32_t af[4];
            ldsm_x4t(af[0], af[1], af[2], af[3], a0);
            mma_bf16(acc0, af, bA);
            ldsm_x4t(af[0], af[1], af[2], af[3], a1);
            mma_bf16(acc1, af, bA);
            ldsm_x4t(af[0], af[1], af[2], af[3], a0 + 1024);
            mma_bf16(acc0, af, bB);
            ldsm_x4t(af[0], af[1], af[2], af[3], a1 + 1024);
            mma_bf16(acc1, af, bB);
        };

        // phase A: hi rows
        mbar_wait_parity(mb_hi, (uint32_t)(t & 1));
#pragma unroll
        for (int p = 0; p < 6; ++p) do_pairAB(kq + 4 * p);

        // phase B: lo rows
        mbar_wait_parity(mb_lo, (uint32_t)(t & 1));
#pragma unroll
        for (int p = 0; p < 6; ++p) do_pair(24 + kq + 4 * p);

#pragma unroll
        for (int rg = 0; rg < 4; ++rg) {
            part[((w * 2 + 0) * 4 + rg) * 32 + lane] = acc0[rg];
            part[((w * 2 + 1) * 4 + rg) * 32 + lane] = acc1[rg];
        }
        __syncthreads();

        // finalize — proven R8 form
        if (tid < 256) {
            float g3[3];
#pragma unroll
            for (int gt = 0; gt < 3; ++gt) {
                float s = 0.f;
#pragma unroll
                for (int k4 = 0; k4 < 4; ++k4) {
                    int wsrc = gt * 4 + k4;
                    s += part[((wsrc * 2 + mtF) * 4 + regF) * 32 + lane_src];
                }
                g3[gt] = s + bsh[gt * 8 + jlf];
            }
            float r = fast_sigmoid(xr + g3[0]);
            float z = fast_sigmoid(xz + g3[1]);
            float n = fast_tanh(xn + r * g3[2]);
            float hv = (1.f - z) * n + z * hprev;
            hprev = hv;
            __nv_bfloat16 hi, lo; split_bf16(hv, hi, lo);
            char* hdst = g_hs[(t & 1) ^ 1];
            *(__nv_bfloat16*)(hdst + hs_goff(jgf, lane)) = hi;
            *(__nv_bfloat16*)(hdst + hs_goff(768 + jgf, lane)) = lo;
            float ov = rv + hv;
            if (out_mode == 0)
                out[(size_t)t * (H_DIM * B_DIM) + (size_t)jgf * B_DIM + lane] = ov;
            else
                out[((size_t)lane * T_STEPS + (T_STEPS - 1 - t)) * H_DIM + jgf] = ov;
            __threadfence();
        }

        // post expect_tx for t+1 BEFORE arriving (senders send only after barrier)
        __syncthreads();
        if (tid == 0 && t + 1 < T_STEPS) {
            mbar_expect_tx(mb_hi, SM_H_HALF);
            mbar_expect_tx(mb_lo, SM_H_HALF);
        }
        unsigned gen = 0;
        if (tid == 0) {
            gen = g_gen;
            if (atomicAdd(&g_arrive, 1) == gridDim.x - 1) {
                atomicExch(&g_arrive, 0);
                __threadfence();
                g_gen = gen + 1;
            }
        }
        if (t + 1 < T_STEPS) prefetch(t + 1);
        if (tid == 0) {
            while (g_gen == gen) { }
            __threadfence();
        }
        __syncthreads();
    }
    // cluster sync before exit: no CTA may leave while peers' multicasts
    // into its smem could still be in flight
    asm volatile("barrier.cluster.arrive.aligned;" ::: "memory");
    asm volatile("barrier.cluster.wait.aligned;" ::: "memory");
}

// ---------------- host launcher ----------------
extern "C" void kernel_launch(void* const* d_in, const int* in_sizes, int n_in,
                              void* d_out, int out_size) {
    const float* x    = (const float*)d_in[0];
    const float* Wih0 = (const float*)d_in[1];
    const float* Whh0 = (const float*)d_in[2];
    const float* bih0 = (const float*)d_in[3];
    const float* bhh0 = (const float*)d_in[4];
    const float* WihS = (const float*)d_in[5];
    const float* WhhS = (const float*)d_in[6];
    const float* bihS = (const float*)d_in[7];
    const float* bhhS = (const float*)d_in[8];
    float* out = (float*)d_out;

    float *xgP, *actA, *actB;
    __nv_bfloat16 *AbigP, *WbigP, *WhhBigP;
    cudaGetSymbolAddress((void**)&xgP, g_xg);
    cudaGetSymbolAddress((void**)&actA, g_actA);
    cudaGetSymbolAddress((void**)&actB, g_actB);
    cudaGetSymbolAddress((void**)&AbigP, g_Abig);
    cudaGetSymbolAddress((void**)&WbigP, g_Wbig);
    cudaGetSymbolAddress((void**)&WhhBigP, g_WhhBig);

    cudaFuncSetAttribute(gemm_tc, cudaFuncAttributeMaxDynamicSharedMemorySize,
                         (int)GEMM_SMEM);
    cudaFuncSetAttribute(gru_rec_tc, cudaFuncAttributeMaxDynamicSharedMemorySize,
                         (int)SM_REC_TOTAL);

    const int nblk = (G_DIM * H_DIM + 255) / 256;
    auto wih_of = [&](int l) { return (l == 0) ? Wih0 : WihS + (size_t)(l - 1) * G_DIM * H_DIM; };
    auto whh_of = [&](int l) { return (l == 0) ? Whh0 : WhhS + (size_t)(l - 1) * G_DIM * H_DIM; };

    // ncu alignment: [0] split_l0 [1] split_x0 [2] gemm0 [3] rec0 (capture slot)
    split_l0<<<2 * nblk, 256>>>(Wih0, Whh0, WbigP, WhhBigP);

    for (int l = 0; l < 4; ++l) {
        const float* bih = (l == 0) ? bih0 : bihS + (size_t)(l - 1) * G_DIM;
        const float* bhh = (l == 0) ? bhh0 : bhhS + (size_t)(l - 1) * G_DIM;

        const float* ain = (l & 1) ? actB : actA;
        float* aout = (l == 3) ? out : ((l & 1) ? actA : actB);

        if (l == 0)
            split_x0<<<T_STEPS, 256>>>(x, AbigP);
        else
            split_act<<<dim3(T_STEPS, H_DIM / 64), 256>>>(ain, AbigP);

        gemm_tc<<<dim3(G_DIM / 128, M_BIG / 128), 256, GEMM_SMEM>>>(
            AbigP, WbigP + (size_t)l * G_DIM * K2, bih, xgP);

        gru_rec_tc<<<RCTAS, RTHR, SM_REC_TOTAL>>>(
            WhhBigP + (size_t)l * G_DIM * KBIG, bhh, xgP,
            (l == 0) ? nullptr : ain, aout, (l == 3) ? 1 : 0);

        if (l < 3) {
            split_w2<<<nblk, 256>>>(wih_of(l + 1), WbigP + (size_t)(l + 1) * G_DIM * K2);
            split_w<<<nblk, 256>>>(whh_of(l + 1), WhhBigP + (size_t)(l + 1) * G_DIM * KBIG);
        }
    }
}

// round 14
// speedup vs baseline: 1.1725x; 1.0745x over previous
#include <cuda_runtime.h>
#include <cuda_bf16.h>
#include <cstdint>

#define T_STEPS 1024
#define H_DIM   768
#define B_DIM   32
#define G_DIM   (3*H_DIM)     // 2304
#define K2      1536          // [hi|lo] packed K for GEMM
#define KBIG    2304          // 3-term K for recurrent W_hh
#define M_BIG   (T_STEPS*B_DIM) // 32768

// ---------------- static device scratch ----------------
__device__ float g_xg[(size_t)T_STEPS * G_DIM * B_DIM];
__device__ float g_actA[(size_t)T_STEPS * H_DIM * B_DIM];
__device__ float g_actB[(size_t)T_STEPS * H_DIM * B_DIM];
__device__ __align__(1024) __nv_bfloat16 g_Abig[(size_t)M_BIG * K2];
__device__ __align__(1024) __nv_bfloat16 g_Wbig[(size_t)4 * G_DIM * K2];
__device__ __align__(1024) __nv_bfloat16 g_WhhBig[(size_t)4 * G_DIM * KBIG];
// h ping-pong, stored in SWIZZLED CHUNK ORDER (see hs_chunk): 96KB each
__device__ __align__(1024) char g_hs[2][1536 * B_DIM * 2];
__device__ unsigned int g_arrive = 0;
__device__ volatile unsigned int g_gen = 0;

// ---------------- bf16 two-term split helpers ----------------
__device__ __forceinline__ void split_bf16(float v, __nv_bfloat16& hi, __nv_bfloat16& lo) {
    hi = __float2bfloat16(v);
    lo = __float2bfloat16(v - __bfloat162float(hi));
}
__device__ __forceinline__ float fast_sigmoid(float x) {
    return __fdividef(1.f, 1.f + __expf(-x));
}
__device__ __forceinline__ float fast_tanh(float x) {
    return 2.f * __fdividef(1.f, 1.f + __expf(-2.f * x)) - 1.f;
}

// swizzled 16B-chunk index for h: row k (64B = 4 chunks), chunk c
__device__ __forceinline__ uint32_t hs_chunk(int k, int c) {
    return (uint32_t)((k >> 1) * 8 + ((((k & 1) << 2) | c) ^ ((k >> 1) & 7)));
}
__device__ __forceinline__ size_t hs_goff(int k, int b) {
    return (size_t)hs_chunk(k, b >> 3) * 16 + (size_t)(b & 7) * 2;
}

// ---------------- split kernels ----------------
__global__ void __launch_bounds__(256) split_x0(const float* __restrict__ x,
                                                __nv_bfloat16* __restrict__ Ab) {
    int t = blockIdx.x;
    for (int i = threadIdx.x; i < 32 * H_DIM; i += 256) {
        int b = i / H_DIM, d = i % H_DIM;
        float v = x[((size_t)b * T_STEPS + t) * H_DIM + d];
        __nv_bfloat16 hi, lo; split_bf16(v, hi, lo);
        size_t r = ((size_t)t * 32 + b) * K2;
        Ab[r + d] = hi;
        Ab[r + 768 + d] = lo;
    }
}

__global__ void __launch_bounds__(256) split_act(const float* __restrict__ act,
                                                 __nv_bfloat16* __restrict__ Ab) {
    __shared__ float sm[64][33];
    int t = blockIdx.x;
    int d0 = blockIdx.y * 64;
    int ts = T_STEPS - 1 - t;
    for (int i = threadIdx.x; i < 64 * 32; i += 256) {
        int dl = i >> 5, b = i & 31;
        sm[dl][b] = act[((size_t)ts * H_DIM + d0 + dl) * B_DIM + b];
    }
    __syncthreads();
    for (int i = threadIdx.x; i < 32 * 64; i += 256) {
        int b = i >> 6, dl = i & 63;
        float v = sm[dl][b];
        __nv_bfloat16 hi, lo; split_bf16(v, hi, lo);
        size_t r = ((size_t)t * 32 + b) * K2;
        Ab[r + d0 + dl] = hi;
        Ab[r + 768 + d0 + dl] = lo;
    }
}

__global__ void __launch_bounds__(256) split_w2(const float* __restrict__ W,
                                                __nv_bfloat16* __restrict__ Wb) {
    int i = blockIdx.x * 256 + threadIdx.x;
    if (i >= G_DIM * H_DIM) return;
    int g = i / H_DIM, d = i % H_DIM;
    float v = W[i];
    __nv_bfloat16 hi, lo; split_bf16(v, hi, lo);
    size_t r = (size_t)g * K2;
    Wb[r + d] = hi;
    Wb[r + 768 + d] = lo;
}

__global__ void __launch_bounds__(256) split_w(const float* __restrict__ W,
                                               __nv_bfloat16* __restrict__ Wb) {
    int i = blockIdx.x * 256 + threadIdx.x;
    if (i >= G_DIM * H_DIM) return;
    int g = i / H_DIM, d = i % H_DIM;
    float v = W[i];
    __nv_bfloat16 hi, lo; split_bf16(v, hi, lo);
    size_t r = (size_t)g * KBIG;
    Wb[r + d] = hi;
    Wb[r + 768 + d] = hi;
    Wb[r + 1536 + d] = lo;
}

__global__ void __launch_bounds__(256) split_l0(const float* __restrict__ Wih0,
                                                const float* __restrict__ Whh0,
                                                __nv_bfloat16* __restrict__ Wb,
                                                __nv_bfloat16* __restrict__ Whh) {
    int half = gridDim.x >> 1;
    if (blockIdx.x < half) {
        int i = blockIdx.x * 256 + threadIdx.x;
        if (i >= G_DIM * H_DIM) return;
        int g = i / H_DIM, d = i % H_DIM;
        float v = Wih0[i];
        __nv_bfloat16 hi, lo; split_bf16(v, hi, lo);
        size_t r = (size_t)g * K2;
        Wb[r + d] = hi;
        Wb[r + 768 + d] = lo;
    } else {
        int i = (blockIdx.x - half) * 256 + threadIdx.x;
        if (i >= G_DIM * H_DIM) return;
        int g = i / H_DIM, d = i % H_DIM;
        float v = Whh0[i];
        __nv_bfloat16 hi, lo; split_bf16(v, hi, lo);
        size_t r = (size_t)g * KBIG;
        Whh[r + d] = hi;
        Whh[r + 768 + d] = hi;
        Whh[r + 1536 + d] = lo;
    }
}

// ---------------- common asm helpers ----------------
__device__ __forceinline__ void cp16(void* s, const void* g) {
    uint32_t sa = (uint32_t)__cvta_generic_to_shared(s);
    asm volatile("cp.async.cg.shared.global [%0], [%1], 16;\n" :: "r"(sa), "l"(g));
}
__device__ __forceinline__ void ldsm_x4(uint32_t& r0, uint32_t& r1, uint32_t& r2, uint32_t& r3,
                                        const __nv_bfloat16* p) {
    uint32_t a = (uint32_t)__cvta_generic_to_shared(p);
    asm volatile("ldmatrix.sync.aligned.m8n8.x4.shared.b16 {%0,%1,%2,%3}, [%4];\n"
                 : "=r"(r0), "=r"(r1), "=r"(r2), "=r"(r3) : "r"(a));
}
__device__ __forceinline__ void ldsm_x4a(uint32_t& r0, uint32_t& r1, uint32_t& r2, uint32_t& r3,
                                         uint32_t a) {
    asm volatile("ldmatrix.sync.aligned.m8n8.x4.shared.b16 {%0,%1,%2,%3}, [%4];\n"
                 : "=r"(r0), "=r"(r1), "=r"(r2), "=r"(r3) : "r"(a));
}
__device__ __forceinline__ void ldsm_x4t(uint32_t& r0, uint32_t& r1, uint32_t& r2, uint32_t& r3,
                                         uint32_t a) {
    asm volatile("ldmatrix.sync.aligned.m8n8.x4.trans.shared.b16 {%0,%1,%2,%3}, [%4];\n"
                 : "=r"(r0), "=r"(r1), "=r"(r2), "=r"(r3) : "r"(a));
}
__device__ __forceinline__ void mma_bf16(float* c, const uint32_t* a, const uint32_t* b) {
    asm volatile("mma.sync.aligned.m16n8k16.row.col.f32.bf16.bf16.f32 "
                 "{%0,%1,%2,%3}, {%4,%5,%6,%7}, {%8,%9}, {%0,%1,%2,%3};\n"
                 : "+f"(c[0]), "+f"(c[1]), "+f"(c[2]), "+f"(c[3])
                 : "r"(a[0]), "r"(a[1]), "r"(a[2]), "r"(a[3]), "r"(b[0]), "r"(b[1]));
}
// bulk async copy with cluster multicast
__device__ __forceinline__ void bulk_cp_mc(uint32_t sdst, const void* gsrc,
                                           uint32_t bytes, uint32_t mbar, uint16_t mask) {
    asm volatile(
        "cp.async.bulk.shared::cluster.global.mbarrier::complete_tx::bytes.multicast::cluster"
        " [%0], [%1], %2, [%3], %4;\n"
        :: "r"(sdst), "l"(gsrc), "r"(bytes), "r"(mbar), "h"(mask) : "memory");
}
__device__ __forceinline__ void mbar_init1(uint32_t mbar) {
    asm volatile("mbarrier.init.shared.b64 [%0], 1;\n" :: "r"(mbar) : "memory");
}
__device__ __forceinline__ void mbar_expect_tx(uint32_t mbar, uint32_t bytes) {
    asm volatile("mbarrier.arrive.expect_tx.shared.b64 _, [%0], %1;\n"
                 :: "r"(mbar), "r"(bytes) : "memory");
}
__device__ __forceinline__ void mbar_wait_parity(uint32_t mbar, uint32_t parity) {
    uint32_t done;
    asm volatile(
        "{\n\t.reg .pred p;\n\t"
        "mbarrier.try_wait.parity.acquire.cta.shared::cta.b64 p, [%1], %2;\n\t"
        "selp.b32 %0, 1, 0, p;\n\t}"
        : "=r"(done) : "r"(mbar), "r"(parity) : "memory");
    if (!done) {
        asm volatile(
            "{\n\t.reg .pred P1;\n\t"
            "WL%=:\n\t"
            "mbarrier.try_wait.parity.acquire.cta.shared::cta.b64 P1, [%0], %1, 0x989680;\n\t"
            "@P1 bra.uni WD%=;\n\t"
            "bra.uni WL%=;\n\t"
            "WD%=:\n\t}"
            :: "r"(mbar), "r"(parity) : "memory");
    }
}
__device__ __forceinline__ uint32_t cluster_rank() {
    uint32_t r;
    asm("mov.u32 %0, %%cluster_ctarank;" : "=r"(r));
    return r;
}

// ---------------- input-projection GEMM (unchanged, best-measured) ----------------
#define SPITCH 40
#define T1 (128 * SPITCH)
#define STG2 (4 * T1)
#define GITER 24

__global__ void __launch_bounds__(256, 1) gemm_tc(
    const __nv_bfloat16* __restrict__ A,
    const __nv_bfloat16* __restrict__ Wb,
    const float* __restrict__ bias,
    float* __restrict__ xg)
{
    extern __shared__ char smem_raw[];
    __nv_bfloat16* sm = (__nv_bfloat16*)smem_raw;

    const int tid = threadIdx.x;
    const int lane = tid & 31;
    const int warp = tid >> 5;
    const int wm = warp >> 1;
    const int wn = warp & 1;
    const int gBase = blockIdx.x * 128;
    const int mBase = blockIdx.y * 128;

    float acc[2][8][4];
#pragma unroll
    for (int i = 0; i < 2; ++i)
#pragma unroll
        for (int j = 0; j < 8; ++j)
#pragma unroll
            for (int k = 0; k < 4; ++k) acc[i][j][k] = 0.f;

    auto load_tile = [&](int stage, int it) {
        __nv_bfloat16* base = sm + stage * STG2;
        int k0 = it * 32;
        int c = tid & 3;
        int rhalf = tid >> 2;
#pragma unroll
        for (int j = 0; j < 8; ++j) {
            int tile = j >> 1;
            int row = (j & 1) * 64 + rhalf;
            const __nv_bfloat16* src =
                (tile < 2 ? A + (size_t)(mBase + row) * K2
                          : Wb + (size_t)(gBase + row) * K2)
                + (tile & 1) * 768 + k0 + c * 8;
            cp16(base + tile * T1 + row * SPITCH + c * 8, src);
        }
    };

#pragma unroll
    for (int s = 0; s < 3; ++s) {
        load_tile(s, s);
        asm volatile("cp.async.commit_group;\n" ::: "memory");
    }

    for (int it = 0; it < GITER; ++it) {
        asm volatile("cp.async.wait_group %0;\n" :: "n"(2) : "memory");
        __syncthreads();
        int itn = it + 3;
        if (itn < GITER) load_tile(itn & 3, itn);
        asm volatile("cp.async.commit_group;\n" ::: "memory");

        const __nv_bfloat16* Ah = sm + (it & 3) * STG2;
        const __nv_bfloat16* Al = Ah + T1;
        const __nv_bfloat16* Wh = Ah + 2 * T1;
        const __nv_bfloat16* Wl = Ah + 3 * T1;
#pragma unroll
        for (int kk = 0; kk < 2; ++kk) {
            uint32_t afh[2][4], afl[2][4];
            uint32_t bfh[8][2], bfl[8][2];
#pragma unroll
            for (int mt = 0; mt < 2; ++mt) {
                int ro = (wm * 32 + mt * 16 + (lane & 15)) * SPITCH + kk * 16 + (lane >> 4) * 8;
                ldsm_x4(afh[mt][0], afh[mt][1], afh[mt][2], afh[mt][3], Ah + ro);
                ldsm_x4(afl[mt][0], afl[mt][1], afl[mt][2], afl[mt][3], Al + ro);
            }
#pragma unroll
            for (int np = 0; np < 4; ++np) {
                int grp = lane >> 3;
                int ro = (wn * 64 + np * 16 + (grp >> 1) * 8 + (lane & 7)) * SPITCH
                       + kk * 16 + (grp & 1) * 8;
                uint32_t r0, r1, r2, r3;
                ldsm_x4(r0, r1, r2, r3, Wh + ro);
                bfh[2 * np][0] = r0; bfh[2 * np][1] = r1;
                bfh[2 * np + 1][0] = r2; bfh[2 * np + 1][1] = r3;
                ldsm_x4(r0, r1, r2, r3, Wl + ro);
                bfl[2 * np][0] = r0; bfl[2 * np][1] = r1;
                bfl[2 * np + 1][0] = r2; bfl[2 * np + 1][1] = r3;
            }
#pragma unroll
            for (int mt = 0; mt < 2; ++mt)
#pragma unroll
                for (int nt = 0; nt < 8; ++nt) {
                    mma_bf16(acc[mt][nt], afh[mt], bfh[nt]);
                    mma_bf16(acc[mt][nt], afl[mt], bfh[nt]);
                    mma_bf16(acc[mt][nt], afh[mt], bfl[nt]);
                }
        }
    }
    asm volatile("cp.async.wait_all;\n" ::: "memory");
    __syncthreads();

    float* ebuf = (float*)smem_raw + warp * (64 * 33);
#pragma unroll
    for (int mt = 0; mt < 2; ++mt)
#pragma unroll
        for (int nt = 0; nt < 8; ++nt) {
            int b0 = mt * 16 + (lane >> 2);
            int gl = nt * 8 + (lane & 3) * 2;
            ebuf[gl * 33 + b0]            = acc[mt][nt][0];
            ebuf[(gl + 1) * 33 + b0]      = acc[mt][nt][1];
            ebuf[gl * 33 + b0 + 8]        = acc[mt][nt][2];
            ebuf[(gl + 1) * 33 + b0 + 8]  = acc[mt][nt][3];
        }
    __syncwarp();
    int t = blockIdx.y * 4 + wm;
    int g0 = gBase + wn * 64;
    size_t obase = (size_t)t * (G_DIM * B_DIM);
#pragma unroll 4
    for (int g = 0; g < 64; ++g) {
        xg[obase + (size_t)(g0 + g) * B_DIM + lane] = ebuf[g * 33 + lane] + bias[g0 + g];
    }
}
#define GEMM_SMEM ((4 * STG2 * 2 > 8 * 64 * 33 * 4) ? 4 * STG2 * 2 : 8 * 64 * 33 * 4)

// ================= tensor-core recurrent kernel (W frags in registers) =================
#define RCTAS 96
#define RTHR  384
#define CLUSTER_SZ 8
#define WPITCH 2312
#define SM_W_BYTES (24 * WPITCH * 2)     // 110976
#define SM_H_OFF   SM_W_BYTES
#define SM_H_BYTES (1536 * 64)           // 98304 (48KB hi + 48KB lo)
#define SM_H_HALF  (SM_H_BYTES / 2)      // 49152
#define SM_H_SLICE (SM_H_BYTES / CLUSTER_SZ)  // 12288 per cluster rank
#define SM_PART_OFF (SM_H_OFF + SM_H_BYTES)
#define SM_PART_BYTES (12 * 2 * 4 * 32 * 4)
#define SM_BSH_OFF (SM_PART_OFF + SM_PART_BYTES)
#define SM_MBAR_OFF (SM_BSH_OFF + 96)
#define SM_REC_TOTAL (SM_BSH_OFF + 128)

__global__ void __launch_bounds__(RTHR, 1) __cluster_dims__(CLUSTER_SZ, 1, 1)
gru_rec_tc(
    const __nv_bfloat16* __restrict__ WhhB,
    const float* __restrict__ bhh,
    const float* __restrict__ xg,
    const float* __restrict__ res,
    float* __restrict__ out,
    int out_mode)
{
    extern __shared__ __align__(1024) char smr[];
    __nv_bfloat16* Wsm = (__nv_bfloat16*)smr;
    const uint32_t hs_base = (uint32_t)__cvta_generic_to_shared(smr + SM_H_OFF);
    float* part = (float*)(smr + SM_PART_OFF);
    float* bsh  = (float*)(smr + SM_BSH_OFF);
    const uint32_t mb_hi = (uint32_t)__cvta_generic_to_shared(smr + SM_MBAR_OFF);
    const uint32_t mb_lo = mb_hi + 8;

    const int tid = threadIdx.x;
    const int lane = tid & 31;
    const int w = tid >> 5;
    const int kq = w & 3;
    const int nt = w >> 2;
    const int cta = blockIdx.x;
    const uint32_t crank = cluster_rank();

    const int jlf = tid >> 5;
    const int jgf = cta * 8 + jlf;

    // W_hh slice -> smem
#pragma unroll
    for (int i = 0; i < 18; ++i) {
        int task = i * RTHR + tid;
        int n = task / 288, c = task % 288;
        int grow = (n >> 3) * H_DIM + cta * 8 + (n & 7);
        cp16(Wsm + n * WPITCH + c * 8, WhhB + (size_t)grow * KBIG + c * 8);
    }
    if (tid < 24) {
        int gt = tid >> 3, jl = tid & 7;
        bsh[tid] = bhh[gt * H_DIM + cta * 8 + jl];
    }
    if (tid < 256) {
        *(__nv_bfloat16*)(g_hs[0] + hs_goff(jgf, lane)) = __float2bfloat16(0.f);
        *(__nv_bfloat16*)(g_hs[0] + hs_goff(768 + jgf, lane)) = __float2bfloat16(0.f);
    }
    if (tid == 0) {
        mbar_init1(mb_hi);
        mbar_init1(mb_lo);
        asm volatile("fence.proxy.async.shared::cta;\n" ::: "memory");
        // expect for step 0 BEFORE the grid barrier (senders issue only after it)
        mbar_expect_tx(mb_hi, SM_H_HALF);
        mbar_expect_tx(mb_lo, SM_H_HALF);
    }
    asm volatile("cp.async.commit_group;\n" ::: "memory");
    asm volatile("cp.async.wait_all;\n" ::: "memory");
    __threadfence();   // publish h zeros — proven writer-side protocol

    // cluster sync: peers' mbarrier init must be visible before any multicast
    asm volatile("barrier.cluster.arrive.aligned;" ::: "memory");
    asm volatile("barrier.cluster.wait.aligned;" ::: "memory");

    // step-0 gate-input prefetch
    float xr = 0.f, xz = 0.f, xn = 0.f, rv = 0.f;
    auto prefetch = [&](int t) {
        if (tid < 256) {
            size_t base = (size_t)t * (G_DIM * B_DIM);
            xr = xg[base + (size_t)(0 * H_DIM + jgf) * B_DIM + lane];
            xz = xg[base + (size_t)(1 * H_DIM + jgf) * B_DIM + lane];
            xn = xg[base + (size_t)(2 * H_DIM + jgf) * B_DIM + lane];
            if (res)
                rv = res[(size_t)(T_STEPS - 1 - t) * (H_DIM * B_DIM) +
                         (size_t)jgf * B_DIM + lane];
        }
    };
    prefetch(0);

    // initial grid barrier — proven R8 form
    __syncthreads();
    if (tid == 0) {
        unsigned gen = g_gen;
        if (atomicAdd(&g_arrive, 1) == gridDim.x - 1) {
            atomicExch(&g_arrive, 0);
            __threadfence();
            g_gen = gen + 1;
        }
        while (g_gen == gen) { }
        __threadfence();
    }
    __syncthreads();

    const int t4 = lane >> 3, r8 = lane & 7;
    const uint32_t w_base = (uint32_t)__cvta_generic_to_shared(Wsm)
                          + (uint32_t)((nt * 8 + r8) * WPITCH * 2 + t4 * 16);
    const int a_roff = ((t4 >> 1) << 3) + r8;
    const int a_c0 = (t4 & 1);

    auto a_addr = [&](int kt, int mt) -> uint32_t {
        int krow = (kt << 4) + a_roff;
        int c = mt * 2 + a_c0;
        return hs_base + hs_chunk(krow, c) * 16;
    };

    // ---- preload step-invariant W fragments into registers (18 ldsm.x4 = 72 regs) ----
    uint32_t wAh[6][4], wAl[6][4], wBt[6][4];
#pragma unroll
    for (int p = 0; p < 6; ++p) {
        int q = kq + 4 * p;
        ldsm_x4a(wAh[p][0], wAh[p][1], wAh[p][2], wAh[p][3],
                 w_base + (uint32_t)(q * 64));
        ldsm_x4a(wAl[p][0], wAl[p][1], wAl[p][2], wAl[p][3],
                 w_base + (uint32_t)((q + 48) * 64));
        ldsm_x4a(wBt[p][0], wBt[p][1], wBt[p][2], wBt[p][3],
                 w_base + (uint32_t)((24 + q) * 64));
    }

    const int mtF = lane >> 4, m_in = lane & 15;
    const int lane_src = (m_in & 7) * 4 + (jlf >> 1);
    const int regF = (jlf & 1) + 2 * (m_in >> 3);
    float hprev = 0.f;

    const uint32_t slice_off = crank * SM_H_SLICE;
    const uint32_t slice_mbar = (crank < 4) ? mb_hi : mb_lo;

    for (int t = 0; t < T_STEPS; ++t) {
        // stage h: this CTA multicasts its 12KB slice to all 8 cluster CTAs
        const char* hsrc = g_hs[t & 1];
        if (tid == 0) {
            bulk_cp_mc(hs_base + slice_off, hsrc + slice_off, SM_H_SLICE,
                       slice_mbar, (uint16_t)0xFF);
        }

        float acc0[4] = {0.f, 0.f, 0.f, 0.f};
        float acc1[4] = {0.f, 0.f, 0.f, 0.f};

        // hi-row pair: A frags shared between Whi (wAh) and Wlo (wAl) terms
        auto do_pairAB = [&](int p) {
            int q = kq + 4 * p;
            uint32_t a0 = a_addr(2 * q, 0);
            uint32_t a1 = a_addr(2 * q, 1);
            uint32_t fA0[4], fA1[4], fB0[4], fB1[4];
            ldsm_x4t(fA0[0], fA0[1], fA0[2], fA0[3], a0);
            ldsm_x4t(fA1[0], fA1[1], fA1[2], fA1[3], a1);
            ldsm_x4t(fB0[0], fB0[1], fB0[2], fB0[3], a0 + 1024);
            ldsm_x4t(fB1[0], fB1[1], fB1[2], fB1[3], a1 + 1024);
            mma_bf16(acc0, fA0, &wAh[p][0]); mma_bf16(acc1, fA1, &wAh[p][0]);
            mma_bf16(acc0, fB0, &wAh[p][2]); mma_bf16(acc1, fB1, &wAh[p][2]);
            mma_bf16(acc0, fA0, &wAl[p][0]); mma_bf16(acc1, fA1, &wAl[p][0]);
            mma_bf16(acc0, fB0, &wAl[p][2]); mma_bf16(acc1, fB1, &wAl[p][2]);
        };
        // lo-row pair (Whi term only, wBt)
        auto do_pair = [&](int p) {
            int q = 24 + kq + 4 * p;
            uint32_t a0 = a_addr(2 * q, 0);
            uint32_t a1 = a_addr(2 * q, 1);
            uint32_t af[4];
            ldsm_x4t(af[0], af[1], af[2], af[3], a0);
            mma_bf16(acc0, af, &wBt[p][0]);
            ldsm_x4t(af[0], af[1], af[2], af[3], a1);
            mma_bf16(acc1, af, &wBt[p][0]);
            ldsm_x4t(af[0], af[1], af[2], af[3], a0 + 1024);
            mma_bf16(acc0, af, &wBt[p][2]);
            ldsm_x4t(af[0], af[1], af[2], af[3], a1 + 1024);
            mma_bf16(acc1, af, &wBt[p][2]);
        };

        // phase A: hi rows
        mbar_wait_parity(mb_hi, (uint32_t)(t & 1));
#pragma unroll
        for (int p = 0; p < 6; ++p) do_pairAB(p);

        // phase B: lo rows
        mbar_wait_parity(mb_lo, (uint32_t)(t & 1));
#pragma unroll
        for (int p = 0; p < 6; ++p) do_pair(p);

#pragma unroll
        for (int rg = 0; rg < 4; ++rg) {
            part[((w * 2 + 0) * 4 + rg) * 32 + lane] = acc0[rg];
            part[((w * 2 + 1) * 4 + rg) * 32 + lane] = acc1[rg];
        }
        __syncthreads();

        // finalize — proven R8 form
        if (tid < 256) {
            float g3[3];
#pragma unroll
            for (int gt = 0; gt < 3; ++gt) {
                float s = 0.f;
#pragma unroll
                for (int k4 = 0; k4 < 4; ++k4) {
                    int wsrc = gt * 4 + k4;
                    s += part[((wsrc * 2 + mtF) * 4 + regF) * 32 + lane_src];
                }
                g3[gt] = s + bsh[gt * 8 + jlf];
            }
            float r = fast_sigmoid(xr + g3[0]);
            float z = fast_sigmoid(xz + g3[1]);
            float n = fast_tanh(xn + r * g3[2]);
            float hv = (1.f - z) * n + z * hprev;
            hprev = hv;
            __nv_bfloat16 hi, lo; split_bf16(hv, hi, lo);
            char* hdst = g_hs[(t & 1) ^ 1];
            *(__nv_bfloat16*)(hdst + hs_goff(jgf, lane)) = hi;
            *(__nv_bfloat16*)(hdst + hs_goff(768 + jgf, lane)) = lo;
            float ov = rv + hv;
            if (out_mode == 0)
                out[(size_t)t * (H_DIM * B_DIM) + (size_t)jgf * B_DIM + lane] = ov;
            else
                out[((size_t)lane * T_STEPS + (T_STEPS - 1 - t)) * H_DIM + jgf] = ov;
            __threadfence();
        }

        // post expect_tx for t+1 BEFORE arriving (senders send only after barrier)
        __syncthreads();
        if (tid == 0 && t + 1 < T_STEPS) {
            mbar_expect_tx(mb_hi, SM_H_HALF);
            mbar_expect_tx(mb_lo, SM_H_HALF);
        }
        unsigned gen = 0;
        if (tid == 0) {
            gen = g_gen;
            if (atomicAdd(&g_arrive, 1) == gridDim.x - 1) {
                atomicExch(&g_arrive, 0);
                __threadfence();
                g_gen = gen + 1;
            }
        }
        if (t + 1 < T_STEPS) prefetch(t + 1);
        if (tid == 0) {
            while (g_gen == gen) { }
            __threadfence();
        }
        __syncthreads();
    }
    // cluster sync before exit
    asm volatile("barrier.cluster.arrive.aligned;" ::: "memory");
    asm volatile("barrier.cluster.wait.aligned;" ::: "memory");
}

// ---------------- host launcher ----------------
extern "C" void kernel_launch(void* const* d_in, const int* in_sizes, int n_in,
                              void* d_out, int out_size) {
    const float* x    = (const float*)d_in[0];
    const float* Wih0 = (const float*)d_in[1];
    const float* Whh0 = (const float*)d_in[2];
    const float* bih0 = (const float*)d_in[3];
    const float* bhh0 = (const float*)d_in[4];
    const float* WihS = (const float*)d_in[5];
    const float* WhhS = (const float*)d_in[6];
    const float* bihS = (const float*)d_in[7];
    const float* bhhS = (const float*)d_in[8];
    float* out = (float*)d_out;

    float *xgP, *actA, *actB;
    __nv_bfloat16 *AbigP, *WbigP, *WhhBigP;
    cudaGetSymbolAddress((void**)&xgP, g_xg);
    cudaGetSymbolAddress((void**)&actA, g_actA);
    cudaGetSymbolAddress((void**)&actB, g_actB);
    cudaGetSymbolAddress((void**)&AbigP, g_Abig);
    cudaGetSymbolAddress((void**)&WbigP, g_Wbig);
    cudaGetSymbolAddress((void**)&WhhBigP, g_WhhBig);

    cudaFuncSetAttribute(gemm_tc, cudaFuncAttributeMaxDynamicSharedMemorySize,
                         (int)GEMM_SMEM);
    cudaFuncSetAttribute(gru_rec_tc, cudaFuncAttributeMaxDynamicSharedMemorySize,
                         (int)SM_REC_TOTAL);

    const int nblk = (G_DIM * H_DIM + 255) / 256;
    auto wih_of = [&](int l) { return (l == 0) ? Wih0 : WihS + (size_t)(l - 1) * G_DIM * H_DIM; };
    auto whh_of = [&](int l) { return (l == 0) ? Whh0 : WhhS + (size_t)(l - 1) * G_DIM * H_DIM; };

    // ncu alignment: [0] split_l0 [1] split_x0 [2] gemm0 [3] rec0 (capture slot)
    split_l0<<<2 * nblk, 256>>>(Wih0, Whh0, WbigP, WhhBigP);

    for (int l = 0; l < 4; ++l) {
        const float* bih = (l == 0) ? bih0 : bihS + (size_t)(l - 1) * G_DIM;
        const float* bhh = (l == 0) ? bhh0 : bhhS + (size_t)(l - 1) * G_DIM;

        const float* ain = (l & 1) ? actB : actA;
        float* aout = (l == 3) ? out : ((l & 1) ? actA : actB);

        if (l == 0)
            split_x0<<<T_STEPS, 256>>>(x, AbigP);
        else
            split_act<<<dim3(T_STEPS, H_DIM / 64), 256>>>(ain, AbigP);

        gemm_tc<<<dim3(G_DIM / 128, M_BIG / 128), 256, GEMM_SMEM>>>(
            AbigP, WbigP + (size_t)l * G_DIM * K2, bih, xgP);

        gru_rec_tc<<<RCTAS, RTHR, SM_REC_TOTAL>>>(
            WhhBigP + (size_t)l * G_DIM * KBIG, bhh, xgP,
            (l == 0) ? nullptr : ain, aout, (l == 3) ? 1 : 0);

        if (l < 3) {
            split_w2<<<nblk, 256>>>(wih_of(l + 1), WbigP + (size_t)(l + 1) * G_DIM * K2);
            split_w<<<nblk, 256>>>(whh_of(l + 1), WhhBigP + (size_t)(l + 1) * G_DIM * KBIG);
        }
    }
}